// round 3
// baseline (speedup 1.0000x reference)
#include <cuda_runtime.h>
#include <math.h>

#define B_   16
#define C_   512
#define L_   1024
#define LP_  1022
#define H_   8
#define DH_  64

// Scratch for Q/K/V conv outputs: [3][B][C][LP] (global, no alloc)
__device__ float g_qkv[3][B_ * C_ * LP_];

// ---------------------------------------------------------------------------
// Fused QKV conv1d as implicit GEMM.
// Tile: 128 oc x 128 l per CTA, 256 threads, 8x8 per thread, ic-chunk 8.
// Ratio: 64 FMA / 16 smem floats = 4.0. Lane-strided l (tl + j*16) -> no conflicts.
// ---------------------------------------------------------------------------
#define XS_STRIDE 132

__global__ __launch_bounds__(256) void conv_kernel(
    const float* __restrict__ x,
    const float* __restrict__ w0, const float* __restrict__ b0,
    const float* __restrict__ w1, const float* __restrict__ b1,
    const float* __restrict__ w2, const float* __restrict__ b2)
{
    __shared__ float Xs[8 * XS_STRIDE];   // 8 ic x 130 positions (+pad)
    __shared__ float Ws[128 * 24];        // 128 oc x (8 ic * 3 taps)

    const int b  = blockIdx.z;
    const int ot = blockIdx.y;            // 0..11 over 1536 out-channels
    const int lt = blockIdx.x;            // 0..7 over positions
    const int l0 = lt * 128;
    const int t  = threadIdx.x;
    const int to = t >> 4;                // 0..15 -> 8 oc rows each
    const int tl = t & 15;                // 0..15 -> 8 l cols each (stride 16)

    const int og_base = ot * 128;
    const int which   = og_base >> 9;     // 0:q 1:k 2:v
    const int oc_base = og_base & 511;
    const float* wp = (which == 0) ? w0 : (which == 1) ? w1 : w2;
    const float* bp = (which == 0) ? b0 : (which == 1) ? b1 : b2;

    float acc[8][8];
#pragma unroll
    for (int i = 0; i < 8; i++)
#pragma unroll
        for (int j = 0; j < 8; j++) acc[i][j] = 0.f;

    for (int ic0 = 0; ic0 < C_; ic0 += 8) {
        // weights: 128 rows x 24 (8 ic x 3 taps, contiguous in gmem)
#pragma unroll
        for (int e = t; e < 128 * 24; e += 256) {
            int o = e / 24, j = e % 24;
            Ws[e] = wp[(oc_base + o) * (C_ * 3) + ic0 * 3 + j];
        }
        // x slice: 8 rows x 130 positions
#pragma unroll
        for (int e = t; e < 8 * XS_STRIDE; e += 256) {
            int ic = e / XS_STRIDE, l = e % XS_STRIDE;
            int lg = l0 + l;
            Xs[e] = (l < 130 && lg < L_) ? x[((b * C_) + (ic0 + ic)) * L_ + lg] : 0.f;
        }
        __syncthreads();

#pragma unroll
        for (int ic = 0; ic < 8; ic++) {
#pragma unroll
            for (int kk = 0; kk < 3; kk++) {
                float wv[8], xv[8];
#pragma unroll
                for (int i = 0; i < 8; i++) wv[i] = Ws[(to * 8 + i) * 24 + ic * 3 + kk];
#pragma unroll
                for (int j = 0; j < 8; j++) xv[j] = Xs[ic * XS_STRIDE + tl + j * 16 + kk];
#pragma unroll
                for (int i = 0; i < 8; i++)
#pragma unroll
                    for (int j = 0; j < 8; j++)
                        acc[i][j] = fmaf(wv[i], xv[j], acc[i][j]);
            }
        }
        __syncthreads();
    }

#pragma unroll
    for (int i = 0; i < 8; i++) {
        const int oc = oc_base + to * 8 + i;
        const float bias = bp[oc];
#pragma unroll
        for (int j = 0; j < 8; j++) {
            const int l = l0 + tl + j * 16;
            if (l < LP_)
                g_qkv[which][((b * C_) + oc) * LP_ + l] = acc[i][j] + bias;
        }
    }
}

// ---------------------------------------------------------------------------
// Flash attention: one CTA per (b, h, q-tile of 128). k-tiles of 64.
// S-phase: 8q x 4k per thread (k lane-strided). O-phase: 4d x 8q (d lane-strided).
// ---------------------------------------------------------------------------
#define Q_STRIDE  130
#define KV_STRIDE 65
#define P_STRIDE  66

__global__ __launch_bounds__(256) void attn_kernel(float* __restrict__ out)
{
    extern __shared__ float sm[];
    float* Qs   = sm;                        // [64 d][130]  (128 q + pad)
    float* Ks   = Qs + 64 * Q_STRIDE;        // [64 d][65]
    float* Vs   = Ks + 64 * KV_STRIDE;       // [64 d][65]
    float* Ps   = Vs + 64 * KV_STRIDE;       // [128 q][66]
    float* mrow = Ps + 128 * P_STRIDE;       // [128]
    float* lrow = mrow + 128;                // [128]
    float* arow = lrow + 128;                // [128]

    const int b  = blockIdx.z;
    const int h  = blockIdx.y;
    const int qt = blockIdx.x;
    const int q0 = qt * 128;
    const int t  = threadIdx.x;
    const int tq = t >> 4;                   // 0..15
    const int tk = t & 15;                   // 0..15

    const float* Qg = g_qkv[0] + ((size_t)(b * C_) + h * DH_) * LP_;
    const float* Kg = g_qkv[1] + ((size_t)(b * C_) + h * DH_) * LP_;
    const float* Vg = g_qkv[2] + ((size_t)(b * C_) + h * DH_) * LP_;

    // load Q tile [64 d][128 q]
#pragma unroll
    for (int e = t; e < 8192; e += 256) {
        int d = e >> 7, q = e & 127;
        int qg = q0 + q;
        Qs[d * Q_STRIDE + q] = (qg < LP_) ? Qg[d * LP_ + qg] : 0.f;
    }
    if (t < 128) { mrow[t] = -1e30f; lrow[t] = 0.f; }

    const float scale = 0.04419417382415922f;  // 1/sqrt(512)

    float o_acc[4][8];                       // [d][q]
#pragma unroll
    for (int i = 0; i < 4; i++)
#pragma unroll
        for (int j = 0; j < 8; j++) o_acc[i][j] = 0.f;

    for (int kt = 0; kt < 16; kt++) {
        const int k0 = kt * 64;
        __syncthreads();   // protect Ks/Vs/Ps from previous iteration readers

#pragma unroll
        for (int e = t; e < 4096; e += 256) {
            int d = e >> 6, kk = e & 63;
            int kg = k0 + kk;
            float kvld = (kg < LP_) ? Kg[d * LP_ + kg] : 0.f;
            float vvld = (kg < LP_) ? Vg[d * LP_ + kg] : 0.f;
            Ks[d * KV_STRIDE + kk] = kvld;
            Vs[d * KV_STRIDE + kk] = vvld;
        }
        __syncthreads();

        // S = (Q^T K) * scale : thread covers q = tq*8+i, k = tk + jj*16
        float s[8][4];
#pragma unroll
        for (int i = 0; i < 8; i++)
#pragma unroll
            for (int jj = 0; jj < 4; jj++) s[i][jj] = 0.f;

        for (int d = 0; d < 64; d++) {
            float qv[8], kv[4];
#pragma unroll
            for (int i = 0; i < 8; i++) qv[i] = Qs[d * Q_STRIDE + tq * 8 + i];
#pragma unroll
            for (int jj = 0; jj < 4; jj++) kv[jj] = Ks[d * KV_STRIDE + tk + jj * 16];
#pragma unroll
            for (int i = 0; i < 8; i++)
#pragma unroll
                for (int jj = 0; jj < 4; jj++)
                    s[i][jj] = fmaf(qv[i], kv[jj], s[i][jj]);
        }
#pragma unroll
        for (int i = 0; i < 8; i++)
#pragma unroll
            for (int jj = 0; jj < 4; jj++) {
                s[i][jj] *= scale;
                if (k0 + tk + jj * 16 >= LP_) s[i][jj] = -1e30f;
            }

        // online softmax; 16 tk-lanes cooperate per q-row
#pragma unroll
        for (int i = 0; i < 8; i++) {
            const int q = tq * 8 + i;
            float rm = fmaxf(fmaxf(s[i][0], s[i][1]), fmaxf(s[i][2], s[i][3]));
#pragma unroll
            for (int off = 8; off > 0; off >>= 1)
                rm = fmaxf(rm, __shfl_xor_sync(0xffffffffu, rm, off, 16));
            const float mold = mrow[q];
            const float mnew = fmaxf(mold, rm);
            float ps = 0.f;
#pragma unroll
            for (int jj = 0; jj < 4; jj++) {
                s[i][jj] = __expf(s[i][jj] - mnew);
                ps += s[i][jj];
            }
#pragma unroll
            for (int off = 8; off > 0; off >>= 1)
                ps += __shfl_xor_sync(0xffffffffu, ps, off, 16);
            if (tk == 0) {
                const float al = __expf(mold - mnew);
                arow[q] = al;
                lrow[q] = lrow[q] * al + ps;
                mrow[q] = mnew;
            }
#pragma unroll
            for (int jj = 0; jj < 4; jj++)
                Ps[q * P_STRIDE + tk + jj * 16] = s[i][jj];
        }
        __syncthreads();

        // O = O*alpha + V @ P^T : thread covers d = tk + i*16, q = tq*8 + j
        float av[8];
#pragma unroll
        for (int j = 0; j < 8; j++) av[j] = arow[tq * 8 + j];
#pragma unroll
        for (int i = 0; i < 4; i++)
#pragma unroll
            for (int j = 0; j < 8; j++) o_acc[i][j] *= av[j];

        for (int kk = 0; kk < 64; kk++) {
            float vv[4], pv[8];
#pragma unroll
            for (int i = 0; i < 4; i++) vv[i] = Vs[(tk + i * 16) * KV_STRIDE + kk];
#pragma unroll
            for (int j = 0; j < 8; j++) pv[j] = Ps[(tq * 8 + j) * P_STRIDE + kk];
#pragma unroll
            for (int i = 0; i < 4; i++)
#pragma unroll
                for (int j = 0; j < 8; j++)
                    o_acc[i][j] = fmaf(vv[i], pv[j], o_acc[i][j]);
        }
    }

    // epilogue: normalize, write out[b, h*64+d, q]
#pragma unroll
    for (int j = 0; j < 8; j++) {
        const int q = q0 + tq * 8 + j;
        if (q >= LP_) continue;
        const float inv = 1.f / lrow[tq * 8 + j];
#pragma unroll
        for (int i = 0; i < 4; i++) {
            const int d = tk + i * 16;
            out[((size_t)(b * C_) + h * DH_ + d) * LP_ + q] = o_acc[i][j] * inv;
        }
    }
}

// ---------------------------------------------------------------------------
extern "C" void kernel_launch(void* const* d_in, const int* in_sizes, int n_in,
                              void* d_out, int out_size)
{
    const float* x  = (const float*)d_in[0];
    const float* w0 = (const float*)d_in[1];
    const float* b0 = (const float*)d_in[2];
    const float* w1 = (const float*)d_in[3];
    const float* b1 = (const float*)d_in[4];
    const float* w2 = (const float*)d_in[5];
    const float* b2 = (const float*)d_in[6];
    float* out = (float*)d_out;

    // Fused QKV conv: grid (l-tiles, oc-tiles over 1536, batch)
    conv_kernel<<<dim3(8, 12, 16), 256>>>(x, w0, b0, w1, b1, w2, b2);

    // Flash attention: grid (q-tiles, heads, batch)
    const size_t smem = (size_t)(64 * Q_STRIDE + 2 * 64 * KV_STRIDE +
                                 128 * P_STRIDE + 3 * 128) * sizeof(float);
    cudaFuncSetAttribute(attn_kernel, cudaFuncAttributeMaxDynamicSharedMemorySize, (int)smem);
    attn_kernel<<<dim3(8, H_, B_), 256, smem>>>(out);
}

// round 5
// speedup vs baseline: 1.7080x; 1.7080x over previous
#include <cuda_runtime.h>
#include <cuda_bf16.h>
#include <cstdint>
#include <math.h>

#define B_   16
#define C_   512
#define L_   1024
#define LP_  1022
#define H_   8
#define DH_  64
#define QP_  1024   // padded l-stride for qkv scratch

// Scratch (global __device__, no allocs):
__device__ float g_qkv[3][B_ * C_ * QP_];
// split weights: [which][tap][oc][ic] bf16
__device__ __nv_bfloat16 g_wh[3 * 3 * C_ * C_];
__device__ __nv_bfloat16 g_wl[3 * 3 * C_ * C_];
// split + transposed x: [B][L][C] bf16
__device__ __nv_bfloat16 g_xth[(size_t)B_ * L_ * C_];
__device__ __nv_bfloat16 g_xtl[(size_t)B_ * L_ * C_];

// ---------------------------------------------------------------------------
__device__ __forceinline__ uint32_t smem_u32(const void* p) {
    uint32_t a;
    asm("{ .reg .u64 t; cvta.to.shared.u64 t, %1; cvt.u32.u64 %0, t; }" : "=r"(a) : "l"(p));
    return a;
}
#define LDSM4(r, addr) \
    asm volatile("ldmatrix.sync.aligned.m8n8.x4.shared.b16 {%0,%1,%2,%3}, [%4];" \
        : "=r"((r)[0]), "=r"((r)[1]), "=r"((r)[2]), "=r"((r)[3]) : "r"(addr))

__device__ __forceinline__ void mma16816(float* d, const uint32_t* a,
                                         uint32_t b0, uint32_t b1) {
    asm volatile("mma.sync.aligned.m16n8k16.row.col.f32.bf16.bf16.f32 "
        "{%0,%1,%2,%3}, {%4,%5,%6,%7}, {%8,%9}, {%0,%1,%2,%3};"
        : "+f"(d[0]), "+f"(d[1]), "+f"(d[2]), "+f"(d[3])
        : "r"(a[0]), "r"(a[1]), "r"(a[2]), "r"(a[3]), "r"(b0), "r"(b1));
}

// ---------------------------------------------------------------------------
// Weight split: w[oc][ic][tap] fp32 -> [which][tap][oc][ic] bf16 hi/lo
// ---------------------------------------------------------------------------
__global__ void wsplit_kernel(const float* __restrict__ w0,
                              const float* __restrict__ w1,
                              const float* __restrict__ w2)
{
    int idx = blockIdx.x * 256 + threadIdx.x;
    if (idx >= 3 * 3 * C_ * C_) return;
    int ic = idx % C_;
    int oc = (idx / C_) % C_;
    int tap = (idx / (C_ * C_)) % 3;
    int which = idx / (3 * C_ * C_);
    const float* w = (which == 0) ? w0 : (which == 1) ? w1 : w2;
    float v = w[(oc * C_ + ic) * 3 + tap];
    __nv_bfloat16 h = __float2bfloat16(v);
    g_wh[idx] = h;
    g_wl[idx] = __float2bfloat16(v - __bfloat162float(h));
}

// ---------------------------------------------------------------------------
// x split + transpose: x[B][C][L] fp32 -> g_xth/g_xtl [B][L][C] bf16
// ---------------------------------------------------------------------------
__global__ __launch_bounds__(256) void xsplit_kernel(const float* __restrict__ x)
{
    __shared__ float tile[32][33];
    const int lb = blockIdx.x * 32, cb = blockIdx.y * 32, b = blockIdx.z;
    const int tx = threadIdx.x & 31, ty = threadIdx.x >> 5;  // ty 0..7
#pragma unroll
    for (int i = 0; i < 32; i += 8)
        tile[ty + i][tx] = x[((size_t)b * C_ + cb + ty + i) * L_ + lb + tx];
    __syncthreads();
#pragma unroll
    for (int i = 0; i < 32; i += 8) {
        const int l = lb + ty + i, c = cb + tx;
        float v = tile[tx][ty + i];
        __nv_bfloat16 h = __float2bfloat16(v);
        size_t o = ((size_t)b * L_ + l) * C_ + c;
        g_xth[o] = h;
        g_xtl[o] = __float2bfloat16(v - __bfloat162float(h));
    }
}

// ---------------------------------------------------------------------------
// Conv via mma.sync (bf16 split, fp32 accum).
// CTA: 128 oc x 128 l. 8 warps (2m x 4n), warp tile 64x32.
// K = 3 taps * 512 ic, chunks of 32. Passes: Ah*Bh + Ah*Bl + Al*Bh.
// smem tiles row stride 40 bf16 (80B) -> conflict-free ldmatrix.
// ---------------------------------------------------------------------------
#define TILE_BYTES 10240          // 128 rows * 80B
#define OFF_AH 0
#define OFF_AL (TILE_BYTES)
#define OFF_BH (2 * TILE_BYTES)
#define OFF_BL (3 * TILE_BYTES)

__global__ __launch_bounds__(256) void conv_mma_kernel(
    const float* __restrict__ bq, const float* __restrict__ bk,
    const float* __restrict__ bv)
{
    __shared__ __align__(16) char smem[4 * TILE_BYTES];
    const uint32_t sb = smem_u32(smem);

    const int tid = threadIdx.x, lane = tid & 31, wid = tid >> 5;
    const int wm = wid >> 2, wn = wid & 3;           // warp: 2m x 4n
    const int lt = blockIdx.x, yb = blockIdx.y, b = blockIdx.z;
    const int which = yb >> 2, oc0 = (yb & 3) * 128;
    const int l0 = lt * 128;
    const float* bias = (which == 0) ? bq : (which == 1) ? bk : bv;

    float acc[4][4][4];
#pragma unroll
    for (int mi = 0; mi < 4; mi++)
#pragma unroll
        for (int nj = 0; nj < 4; nj++)
#pragma unroll
            for (int r = 0; r < 4; r++) acc[mi][nj][r] = 0.f;

    for (int kc = 0; kc < 48; kc++) {
        const int tap = kc >> 4;
        const int ic0 = (kc & 15) * 32;
        __syncthreads();

        // A: [128 oc][32 ic] hi+lo
        const __nv_bfloat16* whp = g_wh + (size_t)((which * 3 + tap) * C_ + oc0) * C_;
        const __nv_bfloat16* wlp = g_wl + (size_t)((which * 3 + tap) * C_ + oc0) * C_;
#pragma unroll
        for (int e = tid; e < 512; e += 256) {
            int row = e >> 2, seg = e & 3;
            size_t so = (size_t)row * C_ + ic0 + seg * 8;
            *(uint4*)(smem + OFF_AH + row * 80 + seg * 16) = *(const uint4*)(whp + so);
            *(uint4*)(smem + OFF_AL + row * 80 + seg * 16) = *(const uint4*)(wlp + so);
        }
        // B: [128 n(l)][32 k(ic)] hi+lo, rows from transposed x at l0+n+tap
#pragma unroll
        for (int e = tid; e < 512; e += 256) {
            int n = e >> 2, seg = e & 3;
            int l = l0 + n + tap;
            uint4 vh = make_uint4(0, 0, 0, 0), vl = make_uint4(0, 0, 0, 0);
            if (l < L_) {
                size_t so = ((size_t)b * L_ + l) * C_ + ic0 + seg * 8;
                vh = *(const uint4*)(g_xth + so);
                vl = *(const uint4*)(g_xtl + so);
            }
            *(uint4*)(smem + OFF_BH + n * 80 + seg * 16) = vh;
            *(uint4*)(smem + OFF_BL + n * 80 + seg * 16) = vl;
        }
        __syncthreads();

#pragma unroll
        for (int ks = 0; ks < 2; ks++) {
            const int colb = (ks * 16 + (lane >> 4) * 8) * 2;  // byte offset in row
            uint32_t ah[4][4], al[4][4], bh[2][4], bl[2][4];
#pragma unroll
            for (int mi = 0; mi < 4; mi++) {
                uint32_t ra = (uint32_t)((wm * 64 + mi * 16 + (lane & 15)) * 80 + colb);
                LDSM4(ah[mi], sb + OFF_AH + ra);
                LDSM4(al[mi], sb + OFF_AL + ra);
            }
#pragma unroll
            for (int ni = 0; ni < 2; ni++) {
                uint32_t rb = (uint32_t)((wn * 32 + ni * 16 + (lane & 15)) * 80 + colb);
                LDSM4(bh[ni], sb + OFF_BH + rb);
                LDSM4(bl[ni], sb + OFF_BL + rb);
            }
#pragma unroll
            for (int mi = 0; mi < 4; mi++)
#pragma unroll
                for (int nj = 0; nj < 4; nj++) {
                    const int ni = nj >> 1, od = nj & 1;
                    mma16816(acc[mi][nj], ah[mi], bh[ni][od], bh[ni][od + 2]);
                    mma16816(acc[mi][nj], ah[mi], bl[ni][od], bl[ni][od + 2]);
                    mma16816(acc[mi][nj], al[mi], bh[ni][od], bh[ni][od + 2]);
                }
        }
    }

    // epilogue: D(m16n8) thread mapping: rows g, g+8; cols (lane&3)*2, +1
    const int g = lane >> 2, tc = lane & 3;
#pragma unroll
    for (int mi = 0; mi < 4; mi++) {
        const int oc_a = oc0 + wm * 64 + mi * 16 + g;
        const float ba = bias[oc_a], bb = bias[oc_a + 8];
        float* ra = &g_qkv[which][((size_t)b * C_ + oc_a) * QP_ + l0];
        float* rb = ra + (size_t)8 * QP_;
#pragma unroll
        for (int nj = 0; nj < 4; nj++) {
            const int lc = wn * 32 + nj * 8 + tc * 2;
            if (l0 + lc < LP_) {
                *(float2*)(ra + lc) = make_float2(acc[mi][nj][0] + ba, acc[mi][nj][1] + ba);
                *(float2*)(rb + lc) = make_float2(acc[mi][nj][2] + bb, acc[mi][nj][3] + bb);
            }
        }
    }
}

// ---------------------------------------------------------------------------
// Flash attention (scalar fp32, R1 config; qkv stride QP_)
// ---------------------------------------------------------------------------
#define QKV_STRIDE 68
#define P_STRIDE   65

__global__ __launch_bounds__(256) void attn_kernel(float* __restrict__ out)
{
    extern __shared__ float sm[];
    float* Qs   = sm;
    float* Ks   = Qs + 64 * QKV_STRIDE;
    float* Vs   = Ks + 64 * QKV_STRIDE;
    float* Ps   = Vs + 64 * QKV_STRIDE;
    float* mrow = Ps + 64 * P_STRIDE;
    float* lrow = mrow + 64;
    float* arow = lrow + 64;

    const int b  = blockIdx.z;
    const int h  = blockIdx.y;
    const int qt = blockIdx.x;
    const int q0 = qt * 64;
    const int t  = threadIdx.x;

    const float* Qg = g_qkv[0] + ((size_t)(b * C_) + h * DH_) * QP_;
    const float* Kg = g_qkv[1] + ((size_t)(b * C_) + h * DH_) * QP_;
    const float* Vg = g_qkv[2] + ((size_t)(b * C_) + h * DH_) * QP_;

    for (int e = t; e < 4096; e += 256) {
        int d = e >> 6, q = e & 63;
        int qg = q0 + q;
        Qs[d * QKV_STRIDE + q] = (qg < LP_) ? Qg[d * QP_ + qg] : 0.f;
    }
    if (t < 64) { mrow[t] = -1e30f; lrow[t] = 0.f; }

    const int tq = t >> 4, tk = t & 15;
    const float scale = 0.04419417382415922f;  // 1/sqrt(512)

    float o_acc[4][4];
#pragma unroll
    for (int i = 0; i < 4; i++)
#pragma unroll
        for (int j = 0; j < 4; j++) o_acc[i][j] = 0.f;

    for (int kt = 0; kt < 16; kt++) {
        const int k0 = kt * 64;
        __syncthreads();

        for (int e = t; e < 4096; e += 256) {
            int d = e >> 6, kk = e & 63;
            int kg = k0 + kk;
            float kvld = (kg < LP_) ? Kg[d * QP_ + kg] : 0.f;
            float vvld = (kg < LP_) ? Vg[d * QP_ + kg] : 0.f;
            Ks[d * QKV_STRIDE + kk] = kvld;
            Vs[d * QKV_STRIDE + kk] = vvld;
        }
        __syncthreads();

        float s[4][4];
#pragma unroll
        for (int i = 0; i < 4; i++)
#pragma unroll
            for (int j = 0; j < 4; j++) s[i][j] = 0.f;

        for (int d = 0; d < 64; d++) {
            float qv[4], kv[4];
#pragma unroll
            for (int i = 0; i < 4; i++) qv[i] = Qs[d * QKV_STRIDE + tq * 4 + i];
#pragma unroll
            for (int j = 0; j < 4; j++) kv[j] = Ks[d * QKV_STRIDE + tk * 4 + j];
#pragma unroll
            for (int i = 0; i < 4; i++)
#pragma unroll
                for (int j = 0; j < 4; j++)
                    s[i][j] = fmaf(qv[i], kv[j], s[i][j]);
        }
#pragma unroll
        for (int i = 0; i < 4; i++)
#pragma unroll
            for (int j = 0; j < 4; j++) {
                s[i][j] *= scale;
                if (k0 + tk * 4 + j >= LP_) s[i][j] = -1e30f;
            }

#pragma unroll
        for (int i = 0; i < 4; i++) {
            const int q = tq * 4 + i;
            float rm = fmaxf(fmaxf(s[i][0], s[i][1]), fmaxf(s[i][2], s[i][3]));
#pragma unroll
            for (int off = 8; off > 0; off >>= 1)
                rm = fmaxf(rm, __shfl_xor_sync(0xffffffffu, rm, off, 16));
            const float mold = mrow[q];
            const float mnew = fmaxf(mold, rm);
            float ps = 0.f;
#pragma unroll
            for (int j = 0; j < 4; j++) {
                s[i][j] = __expf(s[i][j] - mnew);
                ps += s[i][j];
            }
#pragma unroll
            for (int off = 8; off > 0; off >>= 1)
                ps += __shfl_xor_sync(0xffffffffu, ps, off, 16);
            if (tk == 0) {
                const float al = __expf(mold - mnew);
                arow[q] = al;
                lrow[q] = lrow[q] * al + ps;
                mrow[q] = mnew;
            }
#pragma unroll
            for (int j = 0; j < 4; j++)
                Ps[q * P_STRIDE + tk * 4 + j] = s[i][j];
        }
        __syncthreads();

        const int td = tq, tq2 = tk;
        float av[4];
#pragma unroll
        for (int j = 0; j < 4; j++) av[j] = arow[tq2 * 4 + j];
#pragma unroll
        for (int i = 0; i < 4; i++)
#pragma unroll
            for (int j = 0; j < 4; j++) o_acc[i][j] *= av[j];

        for (int kk = 0; kk < 64; kk++) {
            float vv[4], pv[4];
#pragma unroll
            for (int i = 0; i < 4; i++) vv[i] = Vs[(td * 4 + i) * QKV_STRIDE + kk];
#pragma unroll
            for (int j = 0; j < 4; j++) pv[j] = Ps[(tq2 * 4 + j) * P_STRIDE + kk];
#pragma unroll
            for (int i = 0; i < 4; i++)
#pragma unroll
                for (int j = 0; j < 4; j++)
                    o_acc[i][j] = fmaf(vv[i], pv[j], o_acc[i][j]);
        }
    }

    const int td = tq, tq2 = tk;
#pragma unroll
    for (int j = 0; j < 4; j++) {
        const int q = q0 + tq2 * 4 + j;
        if (q >= LP_) continue;
        const float inv = 1.f / lrow[tq2 * 4 + j];
#pragma unroll
        for (int i = 0; i < 4; i++) {
            const int d = td * 4 + i;
            out[((size_t)(b * C_) + h * DH_ + d) * LP_ + q] = o_acc[i][j] * inv;
        }
    }
}

// ---------------------------------------------------------------------------
extern "C" void kernel_launch(void* const* d_in, const int* in_sizes, int n_in,
                              void* d_out, int out_size)
{
    const float* x  = (const float*)d_in[0];
    const float* w0 = (const float*)d_in[1];
    const float* b0 = (const float*)d_in[2];
    const float* w1 = (const float*)d_in[3];
    const float* b1 = (const float*)d_in[4];
    const float* w2 = (const float*)d_in[5];
    const float* b2 = (const float*)d_in[6];
    float* out = (float*)d_out;

    // 1) split weights (bf16 hi/lo, transposed)
    wsplit_kernel<<<(3 * 3 * C_ * C_ + 255) / 256, 256>>>(w0, w1, w2);

    // 2) split + transpose x -> [B][L][C] bf16 hi/lo
    xsplit_kernel<<<dim3(L_ / 32, C_ / 32, B_), 256>>>(x);

    // 3) conv via mma.sync: grid (l-tiles, which*oc-tiles, batch)
    conv_mma_kernel<<<dim3(8, 12, 16), 256>>>(b0, b1, b2);

    // 4) flash attention (scalar fp32)
    const size_t smem = (size_t)(3 * 64 * QKV_STRIDE + 64 * P_STRIDE + 3 * 64) * sizeof(float);
    cudaFuncSetAttribute(attn_kernel, cudaFuncAttributeMaxDynamicSharedMemorySize, (int)smem);
    attn_kernel<<<dim3(16, H_, B_), 256, smem>>>(out);
}

// round 7
// speedup vs baseline: 2.7902x; 1.6336x over previous
#include <cuda_runtime.h>
#include <cuda_bf16.h>
#include <cstdint>
#include <math.h>

#define B_   16
#define C_   512
#define L_   1024
#define LP_  1022
#define H_   8
#define DH_  64
#define QP_  1024

// Scratch (global __device__, zero-init, no allocs)
__device__ float g_qkv[3][B_ * C_ * QP_];
__device__ __align__(16) __nv_bfloat16 g_wh[3 * 3 * C_ * C_];
__device__ __align__(16) __nv_bfloat16 g_wl[3 * 3 * C_ * C_];
__device__ __align__(16) __nv_bfloat16 g_xth[(size_t)B_ * L_ * C_];
__device__ __align__(16) __nv_bfloat16 g_xtl[(size_t)B_ * L_ * C_];
// q/k transposed+split: [which][b][l][c]
__device__ __align__(16) __nv_bfloat16 g_qkth[2][(size_t)B_ * L_ * C_];
__device__ __align__(16) __nv_bfloat16 g_qktl[2][(size_t)B_ * L_ * C_];
// v split in [b][c][l]
__device__ __align__(16) __nv_bfloat16 g_vh[(size_t)B_ * C_ * L_];
__device__ __align__(16) __nv_bfloat16 g_vl[(size_t)B_ * C_ * L_];

// ---------------------------------------------------------------------------
__device__ __forceinline__ uint32_t smem_u32(const void* p) {
    uint32_t a;
    asm("{ .reg .u64 t; cvta.to.shared.u64 t, %1; cvt.u32.u64 %0, t; }" : "=r"(a) : "l"(p));
    return a;
}
#define LDSM4(r, addr) \
    asm volatile("ldmatrix.sync.aligned.m8n8.x4.shared.b16 {%0,%1,%2,%3}, [%4];" \
        : "=r"((r)[0]), "=r"((r)[1]), "=r"((r)[2]), "=r"((r)[3]) : "r"(addr))

__device__ __forceinline__ void mma16816(float* d, const uint32_t* a,
                                         uint32_t b0, uint32_t b1) {
    asm volatile("mma.sync.aligned.m16n8k16.row.col.f32.bf16.bf16.f32 "
        "{%0,%1,%2,%3}, {%4,%5,%6,%7}, {%8,%9}, {%0,%1,%2,%3};"
        : "+f"(d[0]), "+f"(d[1]), "+f"(d[2]), "+f"(d[3])
        : "r"(a[0]), "r"(a[1]), "r"(a[2]), "r"(a[3]), "r"(b0), "r"(b1));
}
#define CPA16(dst, src)      asm volatile("cp.async.cg.shared.global [%0], [%1], 16;" :: "r"(dst), "l"(src))
#define CPA16Z(dst, src, sz) asm volatile("cp.async.cg.shared.global [%0], [%1], 16, %2;" :: "r"(dst), "l"(src), "r"(sz))
#define CPA_COMMIT()         asm volatile("cp.async.commit_group;" ::: "memory")
#define CPA_WAIT0()          asm volatile("cp.async.wait_group 0;" ::: "memory")

__device__ __forceinline__ uint32_t packbf(float lo, float hi) {
    __nv_bfloat162 t = __floats2bfloat162_rn(lo, hi);
    return *reinterpret_cast<uint32_t*>(&t);
}

// ---------------------------------------------------------------------------
// Weight split: w[oc][ic][tap] fp32 -> [which][tap][oc][ic] bf16 hi/lo
// ---------------------------------------------------------------------------
__global__ void wsplit_kernel(const float* __restrict__ w0,
                              const float* __restrict__ w1,
                              const float* __restrict__ w2)
{
    int idx = blockIdx.x * 256 + threadIdx.x;
    if (idx >= 3 * 3 * C_ * C_) return;
    int ic = idx % C_;
    int oc = (idx / C_) % C_;
    int tap = (idx / (C_ * C_)) % 3;
    int which = idx / (3 * C_ * C_);
    const float* w = (which == 0) ? w0 : (which == 1) ? w1 : w2;
    float v = w[(oc * C_ + ic) * 3 + tap];
    __nv_bfloat16 h = __float2bfloat16(v);
    g_wh[idx] = h;
    g_wl[idx] = __float2bfloat16(v - __bfloat162float(h));
}

// ---------------------------------------------------------------------------
// x split + transpose: x[B][C][L] fp32 -> g_xth/g_xtl [B][L][C] bf16
// ---------------------------------------------------------------------------
__global__ __launch_bounds__(256) void xsplit_kernel(const float* __restrict__ x)
{
    __shared__ float tile[32][33];
    const int lb = blockIdx.x * 32, cb = blockIdx.y * 32, b = blockIdx.z;
    const int tx = threadIdx.x & 31, ty = threadIdx.x >> 5;
#pragma unroll
    for (int i = 0; i < 32; i += 8)
        tile[ty + i][tx] = x[((size_t)b * C_ + cb + ty + i) * L_ + lb + tx];
    __syncthreads();
#pragma unroll
    for (int i = 0; i < 32; i += 8) {
        const int l = lb + ty + i, c = cb + tx;
        float v = tile[tx][ty + i];
        __nv_bfloat16 h = __float2bfloat16(v);
        size_t o = ((size_t)b * L_ + l) * C_ + c;
        g_xth[o] = h;
        g_xtl[o] = __float2bfloat16(v - __bfloat162float(h));
    }
}

// ---------------------------------------------------------------------------
// q/k transpose+split: g_qkv[which][b][c][l] -> g_qkth/l[which][b][l][c]
// ---------------------------------------------------------------------------
__global__ __launch_bounds__(256) void qksplit_kernel()
{
    __shared__ float tile[32][33];
    const int lb = blockIdx.x * 32, cb = blockIdx.y * 32;
    const int which = blockIdx.z & 1, b = blockIdx.z >> 1;
    const int tx = threadIdx.x & 31, ty = threadIdx.x >> 5;
    const float* src = g_qkv[which] + (size_t)b * C_ * QP_;
#pragma unroll
    for (int i = 0; i < 32; i += 8)
        tile[ty + i][tx] = src[(size_t)(cb + ty + i) * QP_ + lb + tx];
    __syncthreads();
#pragma unroll
    for (int i = 0; i < 32; i += 8) {
        const int l = lb + ty + i, c = cb + tx;
        float v = tile[tx][ty + i];
        __nv_bfloat16 h = __float2bfloat16(v);
        size_t o = ((size_t)b * L_ + l) * C_ + c;
        g_qkth[which][o] = h;
        g_qktl[which][o] = __float2bfloat16(v - __bfloat162float(h));
    }
}

// ---------------------------------------------------------------------------
// v split (layout preserved): g_qkv[2][b][c][l] -> g_vh/g_vl [b][c][l]
// ---------------------------------------------------------------------------
__global__ void vsplit_kernel()
{
    size_t idx = (size_t)blockIdx.x * 256 + threadIdx.x;
    if (idx >= (size_t)B_ * C_ * L_) return;
    size_t b = idx / (C_ * L_), r = idx % (C_ * L_);
    float v = g_qkv[2][b * C_ * QP_ + (r / L_) * QP_ + (r % L_)];
    __nv_bfloat16 h = __float2bfloat16(v);
    g_vh[idx] = h;
    g_vl[idx] = __float2bfloat16(v - __bfloat162float(h));
}

// ---------------------------------------------------------------------------
// Conv via mma.sync, double-buffered cp.async.
// CTA: 128 oc x 128 l, 8 warps (2m x 4n). K = 3 taps * 512 ic, chunks of 32.
// ---------------------------------------------------------------------------
#define TILEB   10240            // 128 rows * 80B
#define OFF_AH  0
#define OFF_AL  (TILEB)
#define OFF_BH  (2 * TILEB)
#define OFF_BL  (3 * TILEB)
#define STAGEB  (4 * TILEB)      // 40960
#define SM_CONV (2 * STAGEB)

__global__ __launch_bounds__(256) void conv_mma_kernel(
    const float* __restrict__ bq, const float* __restrict__ bk,
    const float* __restrict__ bv)
{
    extern __shared__ __align__(16) char smc[];
    const uint32_t sb = smem_u32(smc);

    const int tid = threadIdx.x, lane = tid & 31, wid = tid >> 5;
    const int wm = wid >> 2, wn = wid & 3;
    const int lt = blockIdx.x, yb = blockIdx.y, b = blockIdx.z;
    const int which = yb >> 2, oc0 = (yb & 3) * 128;
    const int l0 = lt * 128;
    const float* bias = (which == 0) ? bq : (which == 1) ? bk : bv;

    const int arow = tid >> 2, aseg = tid & 3;           // covers e = tid, tid+256

    // stage loader: A [128 oc][32 ic], B [128 l][32 ic], hi+lo
    auto load_stage = [&](int kc, int stg) {
        const int tap = kc >> 4, ic0 = (kc & 15) * 32;
        const uint32_t base = sb + stg * STAGEB;
        const __nv_bfloat16* whp = g_wh + (size_t)((which * 3 + tap) * C_ + oc0) * C_ + ic0;
        const __nv_bfloat16* wlp = g_wl + (size_t)((which * 3 + tap) * C_ + oc0) * C_ + ic0;
#pragma unroll
        for (int k = 0; k < 2; k++) {
            int row = arow + k * 64, seg = aseg;
            uint32_t d = base + OFF_AH + row * 80 + seg * 16;
            CPA16(d, whp + (size_t)row * C_ + seg * 8);
            CPA16(d + (OFF_AL - OFF_AH), wlp + (size_t)row * C_ + seg * 8);
        }
#pragma unroll
        for (int k = 0; k < 2; k++) {
            int n = arow + k * 64, seg = aseg;
            int l = l0 + n + tap;
            uint32_t sz = (l < L_) ? 16u : 0u;
            int lc = (l < L_) ? l : 0;
            size_t so = ((size_t)b * L_ + lc) * C_ + ic0 + seg * 8;
            uint32_t d = base + OFF_BH + n * 80 + seg * 16;
            CPA16Z(d, g_xth + so, sz);
            CPA16Z(d + (OFF_BL - OFF_BH), g_xtl + so, sz);
        }
        CPA_COMMIT();
    };

    float acc[4][4][4];
#pragma unroll
    for (int mi = 0; mi < 4; mi++)
#pragma unroll
        for (int nj = 0; nj < 4; nj++)
#pragma unroll
            for (int r = 0; r < 4; r++) acc[mi][nj][r] = 0.f;

    load_stage(0, 0);
    CPA_WAIT0();
    __syncthreads();

    for (int kc = 0; kc < 48; kc++) {
        const int stg = kc & 1;
        if (kc < 47) load_stage(kc + 1, stg ^ 1);

        const uint32_t base = sb + stg * STAGEB;
#pragma unroll
        for (int ks = 0; ks < 2; ks++) {
            const int colb = (ks * 16 + (lane >> 4) * 8) * 2;
            uint32_t ah[4][4], al[4][4], bh[2][4], bl[2][4];
#pragma unroll
            for (int mi = 0; mi < 4; mi++) {
                uint32_t ra = (uint32_t)((wm * 64 + mi * 16 + (lane & 15)) * 80 + colb);
                LDSM4(ah[mi], base + OFF_AH + ra);
                LDSM4(al[mi], base + OFF_AL + ra);
            }
#pragma unroll
            for (int ni = 0; ni < 2; ni++) {
                uint32_t rb = (uint32_t)((wn * 32 + ni * 16 + (lane & 15)) * 80 + colb);
                LDSM4(bh[ni], base + OFF_BH + rb);
                LDSM4(bl[ni], base + OFF_BL + rb);
            }
#pragma unroll
            for (int mi = 0; mi < 4; mi++)
#pragma unroll
                for (int nj = 0; nj < 4; nj++) {
                    const int ni = nj >> 1, od = nj & 1;
                    mma16816(acc[mi][nj], ah[mi], bh[ni][od], bh[ni][od + 2]);
                    mma16816(acc[mi][nj], ah[mi], bl[ni][od], bl[ni][od + 2]);
                    mma16816(acc[mi][nj], al[mi], bh[ni][od], bh[ni][od + 2]);
                }
        }
        CPA_WAIT0();
        __syncthreads();
    }

    const int g = lane >> 2, tc = lane & 3;
#pragma unroll
    for (int mi = 0; mi < 4; mi++) {
        const int oc_a = oc0 + wm * 64 + mi * 16 + g;
        const float ba = bias[oc_a], bb = bias[oc_a + 8];
        float* ra = &g_qkv[which][((size_t)b * C_ + oc_a) * QP_ + l0];
        float* rb = ra + (size_t)8 * QP_;
#pragma unroll
        for (int nj = 0; nj < 4; nj++) {
            const int lc = wn * 32 + nj * 8 + tc * 2;
            if (l0 + lc < LP_) {
                *(float2*)(ra + lc) = make_float2(acc[mi][nj][0] + ba, acc[mi][nj][1] + ba);
                *(float2*)(rb + lc) = make_float2(acc[mi][nj][2] + bb, acc[mi][nj][3] + bb);
            }
        }
    }
}

// ---------------------------------------------------------------------------
// Tensor-core flash attention. CTA per (b, h, q-tile 128); 8 warps each own
// 16 q-rows. K-tiles of 64. Split-bf16 3-pass for S and PV; P stays in regs.
// ---------------------------------------------------------------------------
#define AT_STR  144              // smem row stride bytes (64 bf16 + pad)
#define A_QH    0
#define A_QL    (128 * AT_STR)           // 18432
#define A_KH    (2 * 128 * AT_STR)       // 36864
#define A_KL    (A_KH + 64 * AT_STR)     // 46080
#define A_VH    (A_KL + 64 * AT_STR)     // 55296
#define A_VL    (A_VH + 64 * AT_STR)     // 64512
#define SM_ATT  (A_VL + 64 * AT_STR)     // 73728

__global__ __launch_bounds__(256, 2) void attn_mma_kernel(float* __restrict__ out)
{
    extern __shared__ __align__(16) char sma[];
    const uint32_t sb = smem_u32(sma);
    const int tid = threadIdx.x, lane = tid & 31, w = tid >> 5;
    const int b = blockIdx.z, h = blockIdx.y, qt = blockIdx.x;
    const int q0 = qt * 128;
    const float scale = 0.04419417382415922f;   // 1/sqrt(512)

    // load Q tile [128 q][64 d] hi/lo
    const __nv_bfloat16* qh = g_qkth[0];
    const __nv_bfloat16* ql = g_qktl[0];
#pragma unroll
    for (int e = tid; e < 1024; e += 256) {
        int row = e >> 3, seg = e & 7;
        size_t so = ((size_t)b * L_ + q0 + row) * C_ + h * DH_ + seg * 8;
        *(uint4*)(sma + A_QH + row * AT_STR + seg * 16) = *(const uint4*)(qh + so);
        *(uint4*)(sma + A_QL + row * AT_STR + seg * 16) = *(const uint4*)(ql + so);
    }

    float mrow[2] = { -1e30f, -1e30f };
    float lrow[2] = { 0.f, 0.f };
    float oacc[8][4];
#pragma unroll
    for (int nj = 0; nj < 8; nj++)
#pragma unroll
        for (int r = 0; r < 4; r++) oacc[nj][r] = 0.f;

    const __nv_bfloat16* kh = g_qkth[1];
    const __nv_bfloat16* kl = g_qktl[1];

    for (int kt = 0; kt < 16; kt++) {
        const int k0 = kt * 64;
        __syncthreads();   // previous iteration's readers done

        // load K [64 keys][64 d] and V [64 d][64 keys], hi/lo
#pragma unroll
        for (int e = tid; e < 512; e += 256) {
            int row = e >> 3, seg = e & 7;
            size_t ko = ((size_t)b * L_ + k0 + row) * C_ + h * DH_ + seg * 8;
            size_t vo = ((size_t)b * C_ + h * DH_ + row) * L_ + k0 + seg * 8;
            *(uint4*)(sma + A_KH + row * AT_STR + seg * 16) = *(const uint4*)(kh + ko);
            *(uint4*)(sma + A_KL + row * AT_STR + seg * 16) = *(const uint4*)(kl + ko);
            *(uint4*)(sma + A_VH + row * AT_STR + seg * 16) = *(const uint4*)(g_vh + vo);
            *(uint4*)(sma + A_VL + row * AT_STR + seg * 16) = *(const uint4*)(g_vl + vo);
        }
        __syncthreads();

        // ---- S = Q K^T (3-pass split) ----
        float sf[8][4];
#pragma unroll
        for (int nj = 0; nj < 8; nj++)
#pragma unroll
            for (int r = 0; r < 4; r++) sf[nj][r] = 0.f;

#pragma unroll
        for (int dc = 0; dc < 4; dc++) {
            uint32_t ah[4], al[4];
            uint32_t aaddr = sb + (uint32_t)((w * 16 + (lane & 15)) * AT_STR + dc * 32 + (lane >> 4) * 16);
            LDSM4(ah, aaddr + A_QH);
            LDSM4(al, aaddr + A_QL);
#pragma unroll
            for (int ks = 0; ks < 4; ks++) {
                uint32_t bh[4], bl[4];
                uint32_t baddr = sb + (uint32_t)((ks * 16 + (lane & 15)) * AT_STR + dc * 32 + (lane >> 4) * 16);
                LDSM4(bh, baddr + A_KH);
                LDSM4(bl, baddr + A_KL);
#pragma unroll
                for (int od = 0; od < 2; od++) {
                    mma16816(sf[ks * 2 + od], ah, bh[od], bh[od + 2]);
                    mma16816(sf[ks * 2 + od], ah, bl[od], bl[od + 2]);
                    mma16816(sf[ks * 2 + od], al, bh[od], bh[od + 2]);
                }
            }
        }

        // scale + mask
#pragma unroll
        for (int nj = 0; nj < 8; nj++)
#pragma unroll
            for (int r = 0; r < 4; r++) {
                int col = k0 + nj * 8 + (lane & 3) * 2 + (r & 1);
                sf[nj][r] = (col < LP_) ? sf[nj][r] * scale : -1e30f;
            }

        // online softmax (rows g=lane>>2 and g+8; quad lanes share a row)
#pragma unroll
        for (int rr = 0; rr < 2; rr++) {
            float rm = -1e30f;
#pragma unroll
            for (int nj = 0; nj < 8; nj++)
                rm = fmaxf(rm, fmaxf(sf[nj][rr * 2], sf[nj][rr * 2 + 1]));
            rm = fmaxf(rm, __shfl_xor_sync(0xffffffffu, rm, 1));
            rm = fmaxf(rm, __shfl_xor_sync(0xffffffffu, rm, 2));
            const float mnew = fmaxf(mrow[rr], rm);
            const float corr = __expf(mrow[rr] - mnew);
            mrow[rr] = mnew;
            float ps = 0.f;
#pragma unroll
            for (int nj = 0; nj < 8; nj++) {
                float e0 = __expf(sf[nj][rr * 2] - mnew);
                float e1 = __expf(sf[nj][rr * 2 + 1] - mnew);
                sf[nj][rr * 2] = e0;
                sf[nj][rr * 2 + 1] = e1;
                ps += e0 + e1;
            }
            ps += __shfl_xor_sync(0xffffffffu, ps, 1);
            ps += __shfl_xor_sync(0xffffffffu, ps, 2);
            lrow[rr] = lrow[rr] * corr + ps;
#pragma unroll
            for (int nj = 0; nj < 8; nj++) {
                oacc[nj][rr * 2]     *= corr;
                oacc[nj][rr * 2 + 1] *= corr;
            }
        }

        // ---- O += P V^T (3-pass; P packed from regs) ----
#pragma unroll
        for (int kc = 0; kc < 4; kc++) {
            uint32_t ap[4], alr[4];
            ap[0] = packbf(sf[2 * kc][0],     sf[2 * kc][1]);
            ap[1] = packbf(sf[2 * kc][2],     sf[2 * kc][3]);
            ap[2] = packbf(sf[2 * kc + 1][0], sf[2 * kc + 1][1]);
            ap[3] = packbf(sf[2 * kc + 1][2], sf[2 * kc + 1][3]);
#pragma unroll
            for (int i = 0; i < 4; i++) {
                float2 bk2 = __bfloat1622float2(*reinterpret_cast<__nv_bfloat162*>(&ap[i]));
                const int njs = 2 * kc + (i >> 1), rb2 = (i & 1) * 2;
                alr[i] = packbf(sf[njs][rb2] - bk2.x, sf[njs][rb2 + 1] - bk2.y);
            }
#pragma unroll
            for (int ds = 0; ds < 4; ds++) {
                uint32_t vh4[4], vl4[4];
                uint32_t vaddr = sb + (uint32_t)((ds * 16 + (lane & 15)) * AT_STR + kc * 32 + (lane >> 4) * 16);
                LDSM4(vh4, vaddr + A_VH);
                LDSM4(vl4, vaddr + A_VL);
#pragma unroll
                for (int od = 0; od < 2; od++) {
                    mma16816(oacc[ds * 2 + od], ap,  vh4[od], vh4[od + 2]);
                    mma16816(oacc[ds * 2 + od], ap,  vl4[od], vl4[od + 2]);
                    mma16816(oacc[ds * 2 + od], alr, vh4[od], vh4[od + 2]);
                }
            }
        }
    }

    // epilogue: normalize + store out[b][h*64+d][q]
    const int g = lane >> 2, tc = lane & 3;
#pragma unroll
    for (int rr = 0; rr < 2; rr++) {
        const int q = q0 + w * 16 + rr * 8 + g;
        if (q >= LP_) continue;
        const float inv = 1.f / lrow[rr];
#pragma unroll
        for (int nj = 0; nj < 8; nj++) {
            const int d = h * DH_ + nj * 8 + tc * 2;
            out[((size_t)b * C_ + d) * LP_ + q]     = oacc[nj][rr * 2] * inv;
            out[((size_t)b * C_ + d + 1) * LP_ + q] = oacc[nj][rr * 2 + 1] * inv;
        }
    }
}

// ---------------------------------------------------------------------------
extern "C" void kernel_launch(void* const* d_in, const int* in_sizes, int n_in,
                              void* d_out, int out_size)
{
    const float* x  = (const float*)d_in[0];
    const float* w0 = (const float*)d_in[1];
    const float* b0 = (const float*)d_in[2];
    const float* w1 = (const float*)d_in[3];
    const float* b1 = (const float*)d_in[4];
    const float* w2 = (const float*)d_in[5];
    const float* b2 = (const float*)d_in[6];
    float* out = (float*)d_out;

    wsplit_kernel<<<(3 * 3 * C_ * C_ + 255) / 256, 256>>>(w0, w1, w2);
    xsplit_kernel<<<dim3(L_ / 32, C_ / 32, B_), 256>>>(x);

    cudaFuncSetAttribute(conv_mma_kernel, cudaFuncAttributeMaxDynamicSharedMemorySize, SM_CONV);
    conv_mma_kernel<<<dim3(8, 12, 16), 256, SM_CONV>>>(b0, b1, b2);

    qksplit_kernel<<<dim3(L_ / 32, C_ / 32, 2 * B_), 256>>>();
    vsplit_kernel<<<(B_ * C_ * L_ + 255) / 256, 256>>>();

    cudaFuncSetAttribute(attn_mma_kernel, cudaFuncAttributeMaxDynamicSharedMemorySize, SM_ATT);
    attn_mma_kernel<<<dim3(8, H_, B_), 256, SM_ATT>>>(out);
}

// round 9
// speedup vs baseline: 2.9087x; 1.0425x over previous
#include <cuda_runtime.h>
#include <cuda_bf16.h>
#include <cstdint>
#include <math.h>

#define B_   16
#define C_   512
#define L_   1024
#define LP_  1022
#define H_   8
#define DH_  64

// Scratch (global __device__, no allocs)
__device__ __align__(16) __nv_bfloat16 g_wh[3 * 3 * C_ * C_];
__device__ __align__(16) __nv_bfloat16 g_wl[3 * 3 * C_ * C_];
__device__ __align__(16) __nv_bfloat16 g_xth[(size_t)B_ * L_ * C_];
__device__ __align__(16) __nv_bfloat16 g_xtl[(size_t)B_ * L_ * C_];
// conv outputs, split bf16, layout [which][b][c][l]
__device__ __align__(16) __nv_bfloat16 g_oh[(size_t)3 * B_ * C_ * L_];
__device__ __align__(16) __nv_bfloat16 g_ol[(size_t)3 * B_ * C_ * L_];

// ---------------------------------------------------------------------------
__device__ __forceinline__ uint32_t smem_u32(const void* p) {
    uint32_t a;
    asm("{ .reg .u64 t; cvta.to.shared.u64 t, %1; cvt.u32.u64 %0, t; }" : "=r"(a) : "l"(p));
    return a;
}
#define LDSM4(r, addr) \
    asm volatile("ldmatrix.sync.aligned.m8n8.x4.shared.b16 {%0,%1,%2,%3}, [%4];" \
        : "=r"((r)[0]), "=r"((r)[1]), "=r"((r)[2]), "=r"((r)[3]) : "r"(addr))
#define LDSM4T(r, addr) \
    asm volatile("ldmatrix.sync.aligned.m8n8.x4.trans.shared.b16 {%0,%1,%2,%3}, [%4];" \
        : "=r"((r)[0]), "=r"((r)[1]), "=r"((r)[2]), "=r"((r)[3]) : "r"(addr))

__device__ __forceinline__ void mma16816(float* d, const uint32_t* a,
                                         uint32_t b0, uint32_t b1) {
    asm volatile("mma.sync.aligned.m16n8k16.row.col.f32.bf16.bf16.f32 "
        "{%0,%1,%2,%3}, {%4,%5,%6,%7}, {%8,%9}, {%0,%1,%2,%3};"
        : "+f"(d[0]), "+f"(d[1]), "+f"(d[2]), "+f"(d[3])
        : "r"(a[0]), "r"(a[1]), "r"(a[2]), "r"(a[3]), "r"(b0), "r"(b1));
}
#define CPA16(dst, src)      asm volatile("cp.async.cg.shared.global [%0], [%1], 16;" :: "r"(dst), "l"(src))
#define CPA16Z(dst, src, sz) asm volatile("cp.async.cg.shared.global [%0], [%1], 16, %2;" :: "r"(dst), "l"(src), "r"(sz))
#define CPA_COMMIT()         asm volatile("cp.async.commit_group;" ::: "memory")
#define CPA_WAIT0()          asm volatile("cp.async.wait_group 0;" ::: "memory")

__device__ __forceinline__ uint32_t packbf(float lo, float hi) {
    __nv_bfloat162 t = __floats2bfloat162_rn(lo, hi);
    return *reinterpret_cast<uint32_t*>(&t);
}

// ---------------------------------------------------------------------------
// Weight split: w[oc][ic][tap] fp32 -> [which][tap][oc][ic] bf16 hi/lo
// ---------------------------------------------------------------------------
__global__ void wsplit_kernel(const float* __restrict__ w0,
                              const float* __restrict__ w1,
                              const float* __restrict__ w2)
{
    int idx = blockIdx.x * 256 + threadIdx.x;
    if (idx >= 3 * 3 * C_ * C_) return;
    int ic = idx % C_;
    int oc = (idx / C_) % C_;
    int tap = (idx / (C_ * C_)) % 3;
    int which = idx / (3 * C_ * C_);
    const float* w = (which == 0) ? w0 : (which == 1) ? w1 : w2;
    float v = w[(oc * C_ + ic) * 3 + tap];
    __nv_bfloat16 h = __float2bfloat16(v);
    g_wh[idx] = h;
    g_wl[idx] = __float2bfloat16(v - __bfloat162float(h));
}

// ---------------------------------------------------------------------------
// x split + transpose: x[B][C][L] fp32 -> g_xth/g_xtl [B][L][C] bf16
// ---------------------------------------------------------------------------
__global__ __launch_bounds__(256) void xsplit_kernel(const float* __restrict__ x)
{
    __shared__ float tile[32][33];
    const int lb = blockIdx.x * 32, cb = blockIdx.y * 32, b = blockIdx.z;
    const int tx = threadIdx.x & 31, ty = threadIdx.x >> 5;
#pragma unroll
    for (int i = 0; i < 32; i += 8)
        tile[ty + i][tx] = x[((size_t)b * C_ + cb + ty + i) * L_ + lb + tx];
    __syncthreads();
#pragma unroll
    for (int i = 0; i < 32; i += 8) {
        const int l = lb + ty + i, c = cb + tx;
        float v = tile[tx][ty + i];
        __nv_bfloat16 h = __float2bfloat16(v);
        size_t o = ((size_t)b * L_ + l) * C_ + c;
        g_xth[o] = h;
        g_xtl[o] = __float2bfloat16(v - __bfloat162float(h));
    }
}

// ---------------------------------------------------------------------------
// Conv via mma.sync, double-buffered cp.async. CTA: 128 oc x 128 l.
// Epilogue splits to bf16 hi/lo and stores [which][b][c][l] directly.
// ---------------------------------------------------------------------------
#define TILEB   10240            // 128 rows * 80B
#define OFF_AH  0
#define OFF_AL  (TILEB)
#define OFF_BH  (2 * TILEB)
#define OFF_BL  (3 * TILEB)
#define STAGEB  (4 * TILEB)
#define SM_CONV (2 * STAGEB)

__global__ __launch_bounds__(256) void conv_mma_kernel(
    const float* __restrict__ bq, const float* __restrict__ bk,
    const float* __restrict__ bv)
{
    extern __shared__ __align__(16) char smc[];
    const uint32_t sb = smem_u32(smc);

    const int tid = threadIdx.x, lane = tid & 31, wid = tid >> 5;
    const int wm = wid >> 2, wn = wid & 3;
    const int lt = blockIdx.x, yb = blockIdx.y, b = blockIdx.z;
    const int which = yb >> 2, oc0 = (yb & 3) * 128;
    const int l0 = lt * 128;
    const float* bias = (which == 0) ? bq : (which == 1) ? bk : bv;

    const int arow = tid >> 2, aseg = tid & 3;

    auto load_stage = [&](int kc, int stg) {
        const int tap = kc >> 4, ic0 = (kc & 15) * 32;
        const uint32_t base = sb + stg * STAGEB;
        const __nv_bfloat16* whp = g_wh + (size_t)((which * 3 + tap) * C_ + oc0) * C_ + ic0;
        const __nv_bfloat16* wlp = g_wl + (size_t)((which * 3 + tap) * C_ + oc0) * C_ + ic0;
#pragma unroll
        for (int k = 0; k < 2; k++) {
            int row = arow + k * 64, seg = aseg;
            uint32_t d = base + OFF_AH + row * 80 + seg * 16;
            CPA16(d, whp + (size_t)row * C_ + seg * 8);
            CPA16(d + (OFF_AL - OFF_AH), wlp + (size_t)row * C_ + seg * 8);
        }
#pragma unroll
        for (int k = 0; k < 2; k++) {
            int n = arow + k * 64, seg = aseg;
            int l = l0 + n + tap;
            uint32_t sz = (l < L_) ? 16u : 0u;
            int lc = (l < L_) ? l : 0;
            size_t so = ((size_t)b * L_ + lc) * C_ + ic0 + seg * 8;
            uint32_t d = base + OFF_BH + n * 80 + seg * 16;
            CPA16Z(d, g_xth + so, sz);
            CPA16Z(d + (OFF_BL - OFF_BH), g_xtl + so, sz);
        }
        CPA_COMMIT();
    };

    float acc[4][4][4];
#pragma unroll
    for (int mi = 0; mi < 4; mi++)
#pragma unroll
        for (int nj = 0; nj < 4; nj++)
#pragma unroll
            for (int r = 0; r < 4; r++) acc[mi][nj][r] = 0.f;

    load_stage(0, 0);
    CPA_WAIT0();
    __syncthreads();

    for (int kc = 0; kc < 48; kc++) {
        const int stg = kc & 1;
        if (kc < 47) load_stage(kc + 1, stg ^ 1);

        const uint32_t base = sb + stg * STAGEB;
#pragma unroll
        for (int ks = 0; ks < 2; ks++) {
            const int colb = (ks * 16 + (lane >> 4) * 8) * 2;
            uint32_t ah[4][4], al[4][4], bh[2][4], bl[2][4];
#pragma unroll
            for (int mi = 0; mi < 4; mi++) {
                uint32_t ra = (uint32_t)((wm * 64 + mi * 16 + (lane & 15)) * 80 + colb);
                LDSM4(ah[mi], base + OFF_AH + ra);
                LDSM4(al[mi], base + OFF_AL + ra);
            }
#pragma unroll
            for (int ni = 0; ni < 2; ni++) {
                uint32_t rb = (uint32_t)((wn * 32 + ni * 16 + (lane & 15)) * 80 + colb);
                LDSM4(bh[ni], base + OFF_BH + rb);
                LDSM4(bl[ni], base + OFF_BL + rb);
            }
#pragma unroll
            for (int mi = 0; mi < 4; mi++)
#pragma unroll
                for (int nj = 0; nj < 4; nj++) {
                    const int ni = nj >> 1, od = nj & 1;
                    mma16816(acc[mi][nj], ah[mi], bh[ni][od], bh[ni][od + 2]);
                    mma16816(acc[mi][nj], ah[mi], bl[ni][od], bl[ni][od + 2]);
                    mma16816(acc[mi][nj], al[mi], bh[ni][od], bh[ni][od + 2]);
                }
        }
        CPA_WAIT0();
        __syncthreads();
    }

    // epilogue: +bias, split to bf16 hi/lo, store [which][b][c][l]
    const int g = lane >> 2, tc = lane & 3;
#pragma unroll
    for (int mi = 0; mi < 4; mi++) {
#pragma unroll
        for (int rr = 0; rr < 2; rr++) {
            const int oc = oc0 + wm * 64 + mi * 16 + g + rr * 8;
            const float bb = bias[oc];
            const size_t rbase = (((size_t)which * B_ + b) * C_ + oc) * L_ + l0;
#pragma unroll
            for (int nj = 0; nj < 4; nj++) {
                const int lc = wn * 32 + nj * 8 + tc * 2;
                float v0 = acc[mi][nj][rr * 2]     + bb;
                float v1 = acc[mi][nj][rr * 2 + 1] + bb;
                __nv_bfloat16 h0 = __float2bfloat16(v0);
                __nv_bfloat16 h1 = __float2bfloat16(v1);
                uint32_t ph = ((uint32_t)__bfloat16_as_ushort(h1) << 16) | __bfloat16_as_ushort(h0);
                uint32_t pl = packbf(v0 - __bfloat162float(h0), v1 - __bfloat162float(h1));
                *(uint32_t*)(g_oh + rbase + lc) = ph;
                *(uint32_t*)(g_ol + rbase + lc) = pl;
            }
        }
    }
}

// ---------------------------------------------------------------------------
// Tensor-core flash attention. Q/K/V all in [c][l] storage; Q,K fragments
// recovered via ldmatrix.trans. 8 warps x 16 q-rows, k-tiles of 64.
// ---------------------------------------------------------------------------
#define QSTR    272              // 128 q * 2B + 16 pad
#define KSTR    144              // 64 * 2B + 16 pad
#define A_QH    0
#define A_QL    (64 * QSTR)                  // 17408
#define A_KH    (2 * 64 * QSTR)              // 34816
#define A_KL    (A_KH + 64 * KSTR)           // 44032
#define A_VH    (A_KL + 64 * KSTR)           // 53248
#define A_VL    (A_VH + 64 * KSTR)           // 62464
#define SM_ATT  (A_VL + 64 * KSTR)           // 71680

__global__ __launch_bounds__(256, 2) void attn_mma_kernel(float* __restrict__ out)
{
    extern __shared__ __align__(16) char sma[];
    const uint32_t sb = smem_u32(sma);
    const int tid = threadIdx.x, lane = tid & 31, w = tid >> 5;
    const int b = blockIdx.z, h = blockIdx.y, qt = blockIdx.x;
    const int q0 = qt * 128;
    const float scale = 0.04419417382415922f;   // 1/sqrt(512)

    const __nv_bfloat16* Qh = g_oh + (((size_t)0 * B_ + b) * C_ + h * DH_) * L_;
    const __nv_bfloat16* Ql = g_ol + (((size_t)0 * B_ + b) * C_ + h * DH_) * L_;
    const __nv_bfloat16* Kh = g_oh + (((size_t)1 * B_ + b) * C_ + h * DH_) * L_;
    const __nv_bfloat16* Kl = g_ol + (((size_t)1 * B_ + b) * C_ + h * DH_) * L_;
    const __nv_bfloat16* Vh = g_oh + (((size_t)2 * B_ + b) * C_ + h * DH_) * L_;
    const __nv_bfloat16* Vl = g_ol + (((size_t)2 * B_ + b) * C_ + h * DH_) * L_;

    // load Q tile [64 d][128 q]
#pragma unroll
    for (int e = tid; e < 1024; e += 256) {
        int row = e >> 4, seg = e & 15;
        size_t so = (size_t)row * L_ + q0 + seg * 8;
        *(uint4*)(sma + A_QH + row * QSTR + seg * 16) = *(const uint4*)(Qh + so);
        *(uint4*)(sma + A_QL + row * QSTR + seg * 16) = *(const uint4*)(Ql + so);
    }

    float mrow[2] = { -1e30f, -1e30f };
    float lrow[2] = { 0.f, 0.f };
    float oacc[8][4];
#pragma unroll
    for (int nj = 0; nj < 8; nj++)
#pragma unroll
        for (int r = 0; r < 4; r++) oacc[nj][r] = 0.f;

    // trans-ldmatrix lane offsets (shared by Q and K loads)
    const int t_dd  = (lane & 7) + ((lane >> 4) & 1) * 8;   // storage row (d)
    const int t_col = ((lane >> 3) & 1) * 8;                 // column offset

    for (int kt = 0; kt < 16; kt++) {
        const int k0 = kt * 64;
        __syncthreads();

        // load K [64 d][64 keys], V [64 d][64 keys]
#pragma unroll
        for (int e = tid; e < 512; e += 256) {
            int row = e >> 3, seg = e & 7;
            size_t so = (size_t)row * L_ + k0 + seg * 8;
            *(uint4*)(sma + A_KH + row * KSTR + seg * 16) = *(const uint4*)(Kh + so);
            *(uint4*)(sma + A_KL + row * KSTR + seg * 16) = *(const uint4*)(Kl + so);
            *(uint4*)(sma + A_VH + row * KSTR + seg * 16) = *(const uint4*)(Vh + so);
            *(uint4*)(sma + A_VL + row * KSTR + seg * 16) = *(const uint4*)(Vl + so);
        }
        __syncthreads();

        // ---- S = Q K^T (3-pass split), trans loads for both operands ----
        float sf[8][4];
#pragma unroll
        for (int nj = 0; nj < 8; nj++)
#pragma unroll
            for (int r = 0; r < 4; r++) sf[nj][r] = 0.f;

#pragma unroll
        for (int dc = 0; dc < 4; dc++) {
            uint32_t ah[4], al[4];
            uint32_t aaddr = sb + A_QH + (uint32_t)((dc * 16 + t_dd) * QSTR + (w * 16 + t_col) * 2);
            LDSM4T(ah, aaddr);
            LDSM4T(al, aaddr + (A_QL - A_QH));
#pragma unroll
            for (int ks = 0; ks < 4; ks++) {
                uint32_t bh[4], bl[4];
                uint32_t baddr = sb + A_KH + (uint32_t)((dc * 16 + t_dd) * KSTR + (ks * 16 + t_col) * 2);
                LDSM4T(bh, baddr);
                LDSM4T(bl, baddr + (A_KL - A_KH));
#pragma unroll
                for (int od = 0; od < 2; od++) {
                    mma16816(sf[ks * 2 + od], ah, bh[od], bh[od + 2]);
                    mma16816(sf[ks * 2 + od], ah, bl[od], bl[od + 2]);
                    mma16816(sf[ks * 2 + od], al, bh[od], bh[od + 2]);
                }
            }
        }

        // scale + mask
#pragma unroll
        for (int nj = 0; nj < 8; nj++)
#pragma unroll
            for (int r = 0; r < 4; r++) {
                int col = k0 + nj * 8 + (lane & 3) * 2 + (r & 1);
                sf[nj][r] = (col < LP_) ? sf[nj][r] * scale : -1e30f;
            }

        // online softmax
#pragma unroll
        for (int rr = 0; rr < 2; rr++) {
            float rm = -1e30f;
#pragma unroll
            for (int nj = 0; nj < 8; nj++)
                rm = fmaxf(rm, fmaxf(sf[nj][rr * 2], sf[nj][rr * 2 + 1]));
            rm = fmaxf(rm, __shfl_xor_sync(0xffffffffu, rm, 1));
            rm = fmaxf(rm, __shfl_xor_sync(0xffffffffu, rm, 2));
            const float mnew = fmaxf(mrow[rr], rm);
            const float corr = __expf(mrow[rr] - mnew);
            mrow[rr] = mnew;
            float ps = 0.f;
#pragma unroll
            for (int nj = 0; nj < 8; nj++) {
                float e0 = __expf(sf[nj][rr * 2] - mnew);
                float e1 = __expf(sf[nj][rr * 2 + 1] - mnew);
                sf[nj][rr * 2] = e0;
                sf[nj][rr * 2 + 1] = e1;
                ps += e0 + e1;
            }
            ps += __shfl_xor_sync(0xffffffffu, ps, 1);
            ps += __shfl_xor_sync(0xffffffffu, ps, 2);
            lrow[rr] = lrow[rr] * corr + ps;
#pragma unroll
            for (int nj = 0; nj < 8; nj++) {
                oacc[nj][rr * 2]     *= corr;
                oacc[nj][rr * 2 + 1] *= corr;
            }
        }

        // ---- O += P V^T (3-pass; P packed from regs) ----
#pragma unroll
        for (int kc = 0; kc < 4; kc++) {
            uint32_t ap[4], alr[4];
            ap[0] = packbf(sf[2 * kc][0],     sf[2 * kc][1]);
            ap[1] = packbf(sf[2 * kc][2],     sf[2 * kc][3]);
            ap[2] = packbf(sf[2 * kc + 1][0], sf[2 * kc + 1][1]);
            ap[3] = packbf(sf[2 * kc + 1][2], sf[2 * kc + 1][3]);
#pragma unroll
            for (int i = 0; i < 4; i++) {
                float2 bk2 = __bfloat1622float2(*reinterpret_cast<__nv_bfloat162*>(&ap[i]));
                const int njs = 2 * kc + (i >> 1), rb2 = (i & 1) * 2;
                alr[i] = packbf(sf[njs][rb2] - bk2.x, sf[njs][rb2 + 1] - bk2.y);
            }
#pragma unroll
            for (int ds = 0; ds < 4; ds++) {
                uint32_t vh4[4], vl4[4];
                uint32_t vaddr = sb + (uint32_t)((ds * 16 + (lane & 15)) * KSTR + kc * 32 + (lane >> 4) * 16);
                LDSM4(vh4, vaddr + A_VH);
                LDSM4(vl4, vaddr + A_VL);
#pragma unroll
                for (int od = 0; od < 2; od++) {
                    mma16816(oacc[ds * 2 + od], ap,  vh4[od], vh4[od + 2]);
                    mma16816(oacc[ds * 2 + od], ap,  vl4[od], vl4[od + 2]);
                    mma16816(oacc[ds * 2 + od], alr, vh4[od], vh4[od + 2]);
                }
            }
        }
    }

    // epilogue: normalize + store out[b][h*64+d][q]
    const int g = lane >> 2, tc = lane & 3;
#pragma unroll
    for (int rr = 0; rr < 2; rr++) {
        const int q = q0 + w * 16 + rr * 8 + g;
        if (q >= LP_) continue;
        const float inv = 1.f / lrow[rr];
#pragma unroll
        for (int nj = 0; nj < 8; nj++) {
            const int d = h * DH_ + nj * 8 + tc * 2;
            out[((size_t)b * C_ + d) * LP_ + q]     = oacc[nj][rr * 2] * inv;
            out[((size_t)b * C_ + d + 1) * LP_ + q] = oacc[nj][rr * 2 + 1] * inv;
        }
    }
}

// ---------------------------------------------------------------------------
extern "C" void kernel_launch(void* const* d_in, const int* in_sizes, int n_in,
                              void* d_out, int out_size)
{
    const float* x  = (const float*)d_in[0];
    const float* w0 = (const float*)d_in[1];
    const float* b0 = (const float*)d_in[2];
    const float* w1 = (const float*)d_in[3];
    const float* b1 = (const float*)d_in[4];
    const float* w2 = (const float*)d_in[5];
    const float* b2 = (const float*)d_in[6];
    float* out = (float*)d_out;

    wsplit_kernel<<<(3 * 3 * C_ * C_ + 255) / 256, 256>>>(w0, w1, w2);
    xsplit_kernel<<<dim3(L_ / 32, C_ / 32, B_), 256>>>(x);

    cudaFuncSetAttribute(conv_mma_kernel, cudaFuncAttributeMaxDynamicSharedMemorySize, SM_CONV);
    conv_mma_kernel<<<dim3(8, 12, 16), 256, SM_CONV>>>(b0, b1, b2);

    cudaFuncSetAttribute(attn_mma_kernel, cudaFuncAttributeMaxDynamicSharedMemorySize, SM_ATT);
    attn_mma_kernel<<<dim3(8, H_, B_), 256, SM_ATT>>>(out);
}

// round 13
// speedup vs baseline: 3.6700x; 1.2617x over previous
#include <cuda_runtime.h>
#include <cuda_bf16.h>
#include <cstdint>
#include <math.h>

#define B_   16
#define C_   512
#define L_   1024
#define LP_  1022
#define H_   8
#define DH_  64

// Scratch (global __device__, no allocs)
// tf32-prerounded fp32 weights, [which*3+tap][oc][ic]
__device__ __align__(16) float g_wt[(size_t)3 * 3 * C_ * C_];
// tf32-prerounded fp32 x, transposed [b][l][c]
__device__ __align__(16) float g_xt[(size_t)B_ * L_ * C_];
// conv outputs, split bf16, layout [which][b][c][l]
__device__ __align__(16) __nv_bfloat16 g_oh[(size_t)3 * B_ * C_ * L_];
__device__ __align__(16) __nv_bfloat16 g_ol[(size_t)3 * B_ * C_ * L_];

// ---------------------------------------------------------------------------
__device__ __forceinline__ uint32_t smem_u32(const void* p) {
    uint32_t a;
    asm("{ .reg .u64 t; cvta.to.shared.u64 t, %1; cvt.u32.u64 %0, t; }" : "=r"(a) : "l"(p));
    return a;
}
#define LDSM4(r, addr) \
    asm volatile("ldmatrix.sync.aligned.m8n8.x4.shared.b16 {%0,%1,%2,%3}, [%4];" \
        : "=r"((r)[0]), "=r"((r)[1]), "=r"((r)[2]), "=r"((r)[3]) : "r"(addr))
#define LDSM4T(r, addr) \
    asm volatile("ldmatrix.sync.aligned.m8n8.x4.trans.shared.b16 {%0,%1,%2,%3}, [%4];" \
        : "=r"((r)[0]), "=r"((r)[1]), "=r"((r)[2]), "=r"((r)[3]) : "r"(addr))

__device__ __forceinline__ void mma16816(float* d, const uint32_t* a,
                                         uint32_t b0, uint32_t b1) {
    asm volatile("mma.sync.aligned.m16n8k16.row.col.f32.bf16.bf16.f32 "
        "{%0,%1,%2,%3}, {%4,%5,%6,%7}, {%8,%9}, {%0,%1,%2,%3};"
        : "+f"(d[0]), "+f"(d[1]), "+f"(d[2]), "+f"(d[3])
        : "r"(a[0]), "r"(a[1]), "r"(a[2]), "r"(a[3]), "r"(b0), "r"(b1));
}
__device__ __forceinline__ void mma1688_tf32(float* d, const uint32_t* a,
                                             uint32_t b0, uint32_t b1) {
    asm volatile("mma.sync.aligned.m16n8k8.row.col.f32.tf32.tf32.f32 "
        "{%0,%1,%2,%3}, {%4,%5,%6,%7}, {%8,%9}, {%0,%1,%2,%3};"
        : "+f"(d[0]), "+f"(d[1]), "+f"(d[2]), "+f"(d[3])
        : "r"(a[0]), "r"(a[1]), "r"(a[2]), "r"(a[3]), "r"(b0), "r"(b1));
}
#define CPA16(dst, src)      asm volatile("cp.async.cg.shared.global [%0], [%1], 16;" :: "r"(dst), "l"(src))
#define CPA16Z(dst, src, sz) asm volatile("cp.async.cg.shared.global [%0], [%1], 16, %2;" :: "r"(dst), "l"(src), "r"(sz))
#define CPA_COMMIT()         asm volatile("cp.async.commit_group;" ::: "memory")
#define CPA_WAIT0()          asm volatile("cp.async.wait_group 0;" ::: "memory")

__device__ __forceinline__ uint32_t packbf(float lo, float hi) {
    __nv_bfloat162 t = __floats2bfloat162_rn(lo, hi);
    return *reinterpret_cast<uint32_t*>(&t);
}
__device__ __forceinline__ float tf32r(float v) {
    uint32_t r;
    asm("cvt.rna.tf32.f32 %0, %1;" : "=r"(r) : "f"(v));
    return __uint_as_float(r);
}

// ---------------------------------------------------------------------------
// Weight transpose + tf32 pre-round: w[oc][ic][tap] -> g_wt[(which*3+tap)][oc][ic]
// ---------------------------------------------------------------------------
__global__ void wtrans_kernel(const float* __restrict__ w0,
                              const float* __restrict__ w1,
                              const float* __restrict__ w2)
{
    int idx = blockIdx.x * 256 + threadIdx.x;
    if (idx >= 3 * 3 * C_ * C_) return;
    int ic = idx % C_;
    int oc = (idx / C_) % C_;
    int tap = (idx / (C_ * C_)) % 3;
    int which = idx / (3 * C_ * C_);
    const float* w = (which == 0) ? w0 : (which == 1) ? w1 : w2;
    g_wt[idx] = tf32r(w[(oc * C_ + ic) * 3 + tap]);
}

// ---------------------------------------------------------------------------
// x transpose + tf32 pre-round: x[B][C][L] -> g_xt[B][L][C]
// ---------------------------------------------------------------------------
__global__ __launch_bounds__(256) void xtrans_kernel(const float* __restrict__ x)
{
    __shared__ float tile[32][33];
    const int lb = blockIdx.x * 32, cb = blockIdx.y * 32, b = blockIdx.z;
    const int tx = threadIdx.x & 31, ty = threadIdx.x >> 5;
#pragma unroll
    for (int i = 0; i < 32; i += 8)
        tile[ty + i][tx] = x[((size_t)b * C_ + cb + ty + i) * L_ + lb + tx];
    __syncthreads();
#pragma unroll
    for (int i = 0; i < 32; i += 8) {
        const int l = lb + ty + i, c = cb + tx;
        g_xt[((size_t)b * L_ + l) * C_ + c] = tf32r(tile[tx][ty + i]);
    }
}

// ---------------------------------------------------------------------------
// Conv via tf32 mma.sync (single pass), double-buffered cp.async.
// CTA: 128 oc x 128 l. K = 3 taps * 512 ic, chunks of 32 (4 k8-steps).
// fp32 tiles, row stride 36 fp32 (144B): conflict-free ldmatrix + aligned cp.async.
// Epilogue splits result to bf16 hi/lo, stores [which][b][c][l].
// ---------------------------------------------------------------------------
#define CROW    144              // bytes per tile row (32 fp32 + 16B pad)
#define CTILEB  (128 * CROW)     // 18432
#define COFF_B  CTILEB
#define CSTAGE  (2 * CTILEB)     // 36864
#define SM_CONV (2 * CSTAGE)     // 73728

__global__ __launch_bounds__(256) void conv_mma_kernel(
    const float* __restrict__ bq, const float* __restrict__ bk,
    const float* __restrict__ bv)
{
    extern __shared__ __align__(16) char smc[];
    const uint32_t sb = smem_u32(smc);

    const int tid = threadIdx.x, lane = tid & 31, wid = tid >> 5;
    const int wm = wid >> 2, wn = wid & 3;
    const int lt = blockIdx.x, yb = blockIdx.y, b = blockIdx.z;
    const int which = yb >> 2, oc0 = (yb & 3) * 128;
    const int l0 = lt * 128;
    const float* bias = (which == 0) ? bq : (which == 1) ? bk : bv;

    auto load_stage = [&](int kc, int stg) {
        const int tap = kc >> 4, ic0 = (kc & 15) * 32;
        const uint32_t base = sb + stg * CSTAGE;
        const float* wp = g_wt + (size_t)((which * 3 + tap) * C_ + oc0) * C_ + ic0;
#pragma unroll
        for (int k = 0; k < 4; k++) {
            int e = tid + k * 256;
            int row = e >> 3, seg = e & 7;
            CPA16(base + row * CROW + seg * 16, wp + (size_t)row * C_ + seg * 4);
        }
#pragma unroll
        for (int k = 0; k < 4; k++) {
            int e = tid + k * 256;
            int n = e >> 3, seg = e & 7;
            int l = l0 + n + tap;
            uint32_t sz = (l < L_) ? 16u : 0u;
            int lc = (l < L_) ? l : 0;
            CPA16Z(base + COFF_B + n * CROW + seg * 16,
                   g_xt + ((size_t)b * L_ + lc) * C_ + ic0 + seg * 4, sz);
        }
        CPA_COMMIT();
    };

    float acc[4][4][4];
#pragma unroll
    for (int mi = 0; mi < 4; mi++)
#pragma unroll
        for (int nj = 0; nj < 4; nj++)
#pragma unroll
            for (int r = 0; r < 4; r++) acc[mi][nj][r] = 0.f;

    load_stage(0, 0);
    CPA_WAIT0();
    __syncthreads();

    // ldmatrix lane mapping for fp32 tiles (8 rows x 4 fp32 cols per 8x8-b16 tile)
    const int fr  = (lane & 7) + ((lane >> 3) & 1) * 8;   // row within 16
    const int fcb = ((lane >> 4) & 1) * 16;               // byte col offset (0 or 16)

    for (int kc = 0; kc < 48; kc++) {
        const int stg = kc & 1;
        if (kc < 47) load_stage(kc + 1, stg ^ 1);

        const uint32_t base = sb + stg * CSTAGE;
#pragma unroll
        for (int ks = 0; ks < 4; ks++) {
            uint32_t a[4][4], bfr[2][4];
#pragma unroll
            for (int mi = 0; mi < 4; mi++) {
                uint32_t ra = base + (uint32_t)((wm * 64 + mi * 16 + fr) * CROW + ks * 32 + fcb);
                LDSM4(a[mi], ra);
            }
#pragma unroll
            for (int njp = 0; njp < 2; njp++) {
                uint32_t rb = base + COFF_B +
                    (uint32_t)((wn * 32 + njp * 16 + fr) * CROW + ks * 32 + fcb);
                LDSM4(bfr[njp], rb);
            }
#pragma unroll
            for (int mi = 0; mi < 4; mi++)
#pragma unroll
                for (int njp = 0; njp < 2; njp++) {
                    mma1688_tf32(acc[mi][njp * 2],     a[mi], bfr[njp][0], bfr[njp][2]);
                    mma1688_tf32(acc[mi][njp * 2 + 1], a[mi], bfr[njp][1], bfr[njp][3]);
                }
        }
        CPA_WAIT0();
        __syncthreads();
    }

    // epilogue: +bias, split to bf16 hi/lo, store [which][b][c][l]
    const int g = lane >> 2, tc = lane & 3;
#pragma unroll
    for (int mi = 0; mi < 4; mi++) {
#pragma unroll
        for (int rr = 0; rr < 2; rr++) {
            const int oc = oc0 + wm * 64 + mi * 16 + g + rr * 8;
            const float bb = bias[oc];
            const size_t rbase = (((size_t)which * B_ + b) * C_ + oc) * L_ + l0;
#pragma unroll
            for (int nj = 0; nj < 4; nj++) {
                const int lc = wn * 32 + nj * 8 + tc * 2;
                float v0 = acc[mi][nj][rr * 2]     + bb;
                float v1 = acc[mi][nj][rr * 2 + 1] + bb;
                __nv_bfloat16 h0 = __float2bfloat16(v0);
                __nv_bfloat16 h1 = __float2bfloat16(v1);
                uint32_t ph = ((uint32_t)__bfloat16_as_ushort(h1) << 16) | __bfloat16_as_ushort(h0);
                uint32_t pl = packbf(v0 - __bfloat162float(h0), v1 - __bfloat162float(h1));
                *(uint32_t*)(g_oh + rbase + lc) = ph;
                *(uint32_t*)(g_ol + rbase + lc) = pl;
            }
        }
    }
}

// ---------------------------------------------------------------------------
// Tensor-core flash attention (unchanged from R8). Q/K/V in [c][l] storage;
// Q,K fragments via ldmatrix.trans. 8 warps x 16 q-rows, k-tiles of 64.
// ---------------------------------------------------------------------------
#define QSTR    272
#define KSTR    144
#define A_QH    0
#define A_QL    (64 * QSTR)
#define A_KH    (2 * 64 * QSTR)
#define A_KL    (A_KH + 64 * KSTR)
#define A_VH    (A_KL + 64 * KSTR)
#define A_VL    (A_VH + 64 * KSTR)
#define SM_ATT  (A_VL + 64 * KSTR)

__global__ __launch_bounds__(256, 2) void attn_mma_kernel(float* __restrict__ out)
{
    extern __shared__ __align__(16) char sma[];
    const uint32_t sb = smem_u32(sma);
    const int tid = threadIdx.x, lane = tid & 31, w = tid >> 5;
    const int b = blockIdx.z, h = blockIdx.y, qt = blockIdx.x;
    const int q0 = qt * 128;
    const float scale = 0.04419417382415922f;   // 1/sqrt(512)

    const __nv_bfloat16* Qh = g_oh + (((size_t)0 * B_ + b) * C_ + h * DH_) * L_;
    const __nv_bfloat16* Ql = g_ol + (((size_t)0 * B_ + b) * C_ + h * DH_) * L_;
    const __nv_bfloat16* Kh = g_oh + (((size_t)1 * B_ + b) * C_ + h * DH_) * L_;
    const __nv_bfloat16* Kl = g_ol + (((size_t)1 * B_ + b) * C_ + h * DH_) * L_;
    const __nv_bfloat16* Vh = g_oh + (((size_t)2 * B_ + b) * C_ + h * DH_) * L_;
    const __nv_bfloat16* Vl = g_ol + (((size_t)2 * B_ + b) * C_ + h * DH_) * L_;

#pragma unroll
    for (int e = tid; e < 1024; e += 256) {
        int row = e >> 4, seg = e & 15;
        size_t so = (size_t)row * L_ + q0 + seg * 8;
        *(uint4*)(sma + A_QH + row * QSTR + seg * 16) = *(const uint4*)(Qh + so);
        *(uint4*)(sma + A_QL + row * QSTR + seg * 16) = *(const uint4*)(Ql + so);
    }

    float mrow[2] = { -1e30f, -1e30f };
    float lrow[2] = { 0.f, 0.f };
    float oacc[8][4];
#pragma unroll
    for (int nj = 0; nj < 8; nj++)
#pragma unroll
        for (int r = 0; r < 4; r++) oacc[nj][r] = 0.f;

    const int t_dd  = (lane & 7) + ((lane >> 4) & 1) * 8;
    const int t_col = ((lane >> 3) & 1) * 8;

    for (int kt = 0; kt < 16; kt++) {
        const int k0 = kt * 64;
        __syncthreads();

#pragma unroll
        for (int e = tid; e < 512; e += 256) {
            int row = e >> 3, seg = e & 7;
            size_t so = (size_t)row * L_ + k0 + seg * 8;
            *(uint4*)(sma + A_KH + row * KSTR + seg * 16) = *(const uint4*)(Kh + so);
            *(uint4*)(sma + A_KL + row * KSTR + seg * 16) = *(const uint4*)(Kl + so);
            *(uint4*)(sma + A_VH + row * KSTR + seg * 16) = *(const uint4*)(Vh + so);
            *(uint4*)(sma + A_VL + row * KSTR + seg * 16) = *(const uint4*)(Vl + so);
        }
        __syncthreads();

        float sf[8][4];
#pragma unroll
        for (int nj = 0; nj < 8; nj++)
#pragma unroll
            for (int r = 0; r < 4; r++) sf[nj][r] = 0.f;

#pragma unroll
        for (int dc = 0; dc < 4; dc++) {
            uint32_t ah[4], al[4];
            uint32_t aaddr = sb + A_QH + (uint32_t)((dc * 16 + t_dd) * QSTR + (w * 16 + t_col) * 2);
            LDSM4T(ah, aaddr);
            LDSM4T(al, aaddr + (A_QL - A_QH));
#pragma unroll
            for (int ks = 0; ks < 4; ks++) {
                uint32_t bh[4], bl[4];
                uint32_t baddr = sb + A_KH + (uint32_t)((dc * 16 + t_dd) * KSTR + (ks * 16 + t_col) * 2);
                LDSM4T(bh, baddr);
                LDSM4T(bl, baddr + (A_KL - A_KH));
#pragma unroll
                for (int od = 0; od < 2; od++) {
                    mma16816(sf[ks * 2 + od], ah, bh[od], bh[od + 2]);
                    mma16816(sf[ks * 2 + od], ah, bl[od], bl[od + 2]);
                    mma16816(sf[ks * 2 + od], al, bh[od], bh[od + 2]);
                }
            }
        }

#pragma unroll
        for (int nj = 0; nj < 8; nj++)
#pragma unroll
            for (int r = 0; r < 4; r++) {
                int col = k0 + nj * 8 + (lane & 3) * 2 + (r & 1);
                sf[nj][r] = (col < LP_) ? sf[nj][r] * scale : -1e30f;
            }

#pragma unroll
        for (int rr = 0; rr < 2; rr++) {
            float rm = -1e30f;
#pragma unroll
            for (int nj = 0; nj < 8; nj++)
                rm = fmaxf(rm, fmaxf(sf[nj][rr * 2], sf[nj][rr * 2 + 1]));
            rm = fmaxf(rm, __shfl_xor_sync(0xffffffffu, rm, 1));
            rm = fmaxf(rm, __shfl_xor_sync(0xffffffffu, rm, 2));
            const float mnew = fmaxf(mrow[rr], rm);
            const float corr = __expf(mrow[rr] - mnew);
            mrow[rr] = mnew;
            float ps = 0.f;
#pragma unroll
            for (int nj = 0; nj < 8; nj++) {
                float e0 = __expf(sf[nj][rr * 2] - mnew);
                float e1 = __expf(sf[nj][rr * 2 + 1] - mnew);
                sf[nj][rr * 2] = e0;
                sf[nj][rr * 2 + 1] = e1;
                ps += e0 + e1;
            }
            ps += __shfl_xor_sync(0xffffffffu, ps, 1);
            ps += __shfl_xor_sync(0xffffffffu, ps, 2);
            lrow[rr] = lrow[rr] * corr + ps;
#pragma unroll
            for (int nj = 0; nj < 8; nj++) {
                oacc[nj][rr * 2]     *= corr;
                oacc[nj][rr * 2 + 1] *= corr;
            }
        }

#pragma unroll
        for (int kc = 0; kc < 4; kc++) {
            uint32_t ap[4], alr[4];
            ap[0] = packbf(sf[2 * kc][0],     sf[2 * kc][1]);
            ap[1] = packbf(sf[2 * kc][2],     sf[2 * kc][3]);
            ap[2] = packbf(sf[2 * kc + 1][0], sf[2 * kc + 1][1]);
            ap[3] = packbf(sf[2 * kc + 1][2], sf[2 * kc + 1][3]);
#pragma unroll
            for (int i = 0; i < 4; i++) {
                float2 bk2 = __bfloat1622float2(*reinterpret_cast<__nv_bfloat162*>(&ap[i]));
                const int njs = 2 * kc + (i >> 1), rb2 = (i & 1) * 2;
                alr[i] = packbf(sf[njs][rb2] - bk2.x, sf[njs][rb2 + 1] - bk2.y);
            }
#pragma unroll
            for (int ds = 0; ds < 4; ds++) {
                uint32_t vh4[4], vl4[4];
                uint32_t vaddr = sb + (uint32_t)((ds * 16 + (lane & 15)) * KSTR + kc * 32 + (lane >> 4) * 16);
                LDSM4(vh4, vaddr + A_VH);
                LDSM4(vl4, vaddr + A_VL);
#pragma unroll
                for (int od = 0; od < 2; od++) {
                    mma16816(oacc[ds * 2 + od], ap,  vh4[od], vh4[od + 2]);
                    mma16816(oacc[ds * 2 + od], ap,  vl4[od], vl4[od + 2]);
                    mma16816(oacc[ds * 2 + od], alr, vh4[od], vh4[od + 2]);
                }
            }
        }
    }

    const int g = lane >> 2, tc = lane & 3;
#pragma unroll
    for (int rr = 0; rr < 2; rr++) {
        const int q = q0 + w * 16 + rr * 8 + g;
        if (q >= LP_) continue;
        const float inv = 1.f / lrow[rr];
#pragma unroll
        for (int nj = 0; nj < 8; nj++) {
            const int d = h * DH_ + nj * 8 + tc * 2;
            out[((size_t)b * C_ + d) * LP_ + q]     = oacc[nj][rr * 2] * inv;
            out[((size_t)b * C_ + d + 1) * LP_ + q] = oacc[nj][rr * 2 + 1] * inv;
        }
    }
}

// ---------------------------------------------------------------------------
extern "C" void kernel_launch(void* const* d_in, const int* in_sizes, int n_in,
                              void* d_out, int out_size)
{
    const float* x  = (const float*)d_in[0];
    const float* w0 = (const float*)d_in[1];
    const float* b0 = (const float*)d_in[2];
    const float* w1 = (const float*)d_in[3];
    const float* b1 = (const float*)d_in[4];
    const float* w2 = (const float*)d_in[5];
    const float* b2 = (const float*)d_in[6];
    float* out = (float*)d_out;

    wtrans_kernel<<<(3 * 3 * C_ * C_ + 255) / 256, 256>>>(w0, w1, w2);
    xtrans_kernel<<<dim3(L_ / 32, C_ / 32, B_), 256>>>(x);

    cudaFuncSetAttribute(conv_mma_kernel, cudaFuncAttributeMaxDynamicSharedMemorySize, SM_CONV);
    conv_mma_kernel<<<dim3(8, 12, 16), 256, SM_CONV>>>(b0, b1, b2);

    cudaFuncSetAttribute(attn_mma_kernel, cudaFuncAttributeMaxDynamicSharedMemorySize, SM_ATT);
    attn_mma_kernel<<<dim3(8, H_, B_), 256, SM_ATT>>>(out);
}

// round 14
// speedup vs baseline: 3.7665x; 1.0263x over previous
#include <cuda_runtime.h>
#include <cuda_bf16.h>
#include <cstdint>
#include <math.h>

#define B_   16
#define C_   512
#define L_   1024
#define LP_  1022
#define H_   8
#define DH_  64

// Scratch (global __device__, no allocs)
__device__ __align__(16) float g_wt[(size_t)3 * 3 * C_ * C_];   // tf32 weights [which*3+tap][oc][ic]
__device__ __align__(16) float g_xt[(size_t)B_ * L_ * C_];       // tf32 x [b][l][c]
__device__ __align__(16) __nv_bfloat16 g_oh[(size_t)3 * B_ * C_ * L_];  // conv out hi [which][b][c][l]
__device__ __align__(16) __nv_bfloat16 g_ol[(size_t)3 * B_ * C_ * L_];  // conv out lo

// ---------------------------------------------------------------------------
__device__ __forceinline__ uint32_t smem_u32(const void* p) {
    uint32_t a;
    asm("{ .reg .u64 t; cvta.to.shared.u64 t, %1; cvt.u32.u64 %0, t; }" : "=r"(a) : "l"(p));
    return a;
}
#define LDSM4(r, addr) \
    asm volatile("ldmatrix.sync.aligned.m8n8.x4.shared.b16 {%0,%1,%2,%3}, [%4];" \
        : "=r"((r)[0]), "=r"((r)[1]), "=r"((r)[2]), "=r"((r)[3]) : "r"(addr))
#define LDSM4T(r, addr) \
    asm volatile("ldmatrix.sync.aligned.m8n8.x4.trans.shared.b16 {%0,%1,%2,%3}, [%4];" \
        : "=r"((r)[0]), "=r"((r)[1]), "=r"((r)[2]), "=r"((r)[3]) : "r"(addr))

__device__ __forceinline__ void mma16816(float* d, const uint32_t* a,
                                         uint32_t b0, uint32_t b1) {
    asm volatile("mma.sync.aligned.m16n8k16.row.col.f32.bf16.bf16.f32 "
        "{%0,%1,%2,%3}, {%4,%5,%6,%7}, {%8,%9}, {%0,%1,%2,%3};"
        : "+f"(d[0]), "+f"(d[1]), "+f"(d[2]), "+f"(d[3])
        : "r"(a[0]), "r"(a[1]), "r"(a[2]), "r"(a[3]), "r"(b0), "r"(b1));
}
__device__ __forceinline__ void mma1688_tf32(float* d, const uint32_t* a,
                                             uint32_t b0, uint32_t b1) {
    asm volatile("mma.sync.aligned.m16n8k8.row.col.f32.tf32.tf32.f32 "
        "{%0,%1,%2,%3}, {%4,%5,%6,%7}, {%8,%9}, {%0,%1,%2,%3};"
        : "+f"(d[0]), "+f"(d[1]), "+f"(d[2]), "+f"(d[3])
        : "r"(a[0]), "r"(a[1]), "r"(a[2]), "r"(a[3]), "r"(b0), "r"(b1));
}
#define CPA16(dst, src)      asm volatile("cp.async.cg.shared.global [%0], [%1], 16;" :: "r"(dst), "l"(src))
#define CPA16Z(dst, src, sz) asm volatile("cp.async.cg.shared.global [%0], [%1], 16, %2;" :: "r"(dst), "l"(src), "r"(sz))
#define CPA_COMMIT()         asm volatile("cp.async.commit_group;" ::: "memory")
#define CPA_WAIT0()          asm volatile("cp.async.wait_group 0;" ::: "memory")

__device__ __forceinline__ uint32_t packbf(float lo, float hi) {
    __nv_bfloat162 t = __floats2bfloat162_rn(lo, hi);
    return *reinterpret_cast<uint32_t*>(&t);
}
__device__ __forceinline__ float tf32r(float v) {
    uint32_t r;
    asm("cvt.rna.tf32.f32 %0, %1;" : "=r"(r) : "f"(v));
    return __uint_as_float(r);
}

// ---------------------------------------------------------------------------
__global__ void wtrans_kernel(const float* __restrict__ w0,
                              const float* __restrict__ w1,
                              const float* __restrict__ w2)
{
    int idx = blockIdx.x * 256 + threadIdx.x;
    if (idx >= 3 * 3 * C_ * C_) return;
    int ic = idx % C_;
    int oc = (idx / C_) % C_;
    int tap = (idx / (C_ * C_)) % 3;
    int which = idx / (3 * C_ * C_);
    const float* w = (which == 0) ? w0 : (which == 1) ? w1 : w2;
    g_wt[idx] = tf32r(w[(oc * C_ + ic) * 3 + tap]);
}

__global__ __launch_bounds__(256) void xtrans_kernel(const float* __restrict__ x)
{
    __shared__ float tile[32][33];
    const int lb = blockIdx.x * 32, cb = blockIdx.y * 32, b = blockIdx.z;
    const int tx = threadIdx.x & 31, ty = threadIdx.x >> 5;
#pragma unroll
    for (int i = 0; i < 32; i += 8)
        tile[ty + i][tx] = x[((size_t)b * C_ + cb + ty + i) * L_ + lb + tx];
    __syncthreads();
#pragma unroll
    for (int i = 0; i < 32; i += 8) {
        const int l = lb + ty + i, c = cb + tx;
        g_xt[((size_t)b * L_ + l) * C_ + c] = tf32r(tile[tx][ty + i]);
    }
}

// ---------------------------------------------------------------------------
// Conv via tf32 mma.sync (single pass), double-buffered cp.async.
// ---------------------------------------------------------------------------
#define CROW    144
#define CTILEB  (128 * CROW)
#define COFF_B  CTILEB
#define CSTAGE  (2 * CTILEB)
#define SM_CONV (2 * CSTAGE)

__global__ __launch_bounds__(256, 2) void conv_mma_kernel(
    const float* __restrict__ bq, const float* __restrict__ bk,
    const float* __restrict__ bv)
{
    extern __shared__ __align__(16) char smc[];
    const uint32_t sb = smem_u32(smc);

    const int tid = threadIdx.x, lane = tid & 31, wid = tid >> 5;
    const int wm = wid >> 2, wn = wid & 3;
    const int lt = blockIdx.x, yb = blockIdx.y, b = blockIdx.z;
    const int which = yb >> 2, oc0 = (yb & 3) * 128;
    const int l0 = lt * 128;
    const float* bias = (which == 0) ? bq : (which == 1) ? bk : bv;

    auto load_stage = [&](int kc, int stg) {
        const int tap = kc >> 4, ic0 = (kc & 15) * 32;
        const uint32_t base = sb + stg * CSTAGE;
        const float* wp = g_wt + (size_t)((which * 3 + tap) * C_ + oc0) * C_ + ic0;
#pragma unroll
        for (int k = 0; k < 4; k++) {
            int e = tid + k * 256;
            int row = e >> 3, seg = e & 7;
            CPA16(base + row * CROW + seg * 16, wp + (size_t)row * C_ + seg * 4);
        }
#pragma unroll
        for (int k = 0; k < 4; k++) {
            int e = tid + k * 256;
            int n = e >> 3, seg = e & 7;
            int l = l0 + n + tap;
            uint32_t sz = (l < L_) ? 16u : 0u;
            int lc = (l < L_) ? l : 0;
            CPA16Z(base + COFF_B + n * CROW + seg * 16,
                   g_xt + ((size_t)b * L_ + lc) * C_ + ic0 + seg * 4, sz);
        }
        CPA_COMMIT();
    };

    float acc[4][4][4];
#pragma unroll
    for (int mi = 0; mi < 4; mi++)
#pragma unroll
        for (int nj = 0; nj < 4; nj++)
#pragma unroll
            for (int r = 0; r < 4; r++) acc[mi][nj][r] = 0.f;

    load_stage(0, 0);
    CPA_WAIT0();
    __syncthreads();

    const int fr  = (lane & 7) + ((lane >> 3) & 1) * 8;
    const int fcb = ((lane >> 4) & 1) * 16;

    for (int kc = 0; kc < 48; kc++) {
        const int stg = kc & 1;
        if (kc < 47) load_stage(kc + 1, stg ^ 1);

        const uint32_t base = sb + stg * CSTAGE;
#pragma unroll
        for (int ks = 0; ks < 4; ks++) {
            uint32_t a[4][4], bfr[2][4];
#pragma unroll
            for (int mi = 0; mi < 4; mi++) {
                uint32_t ra = base + (uint32_t)((wm * 64 + mi * 16 + fr) * CROW + ks * 32 + fcb);
                LDSM4(a[mi], ra);
            }
#pragma unroll
            for (int njp = 0; njp < 2; njp++) {
                uint32_t rb = base + COFF_B +
                    (uint32_t)((wn * 32 + njp * 16 + fr) * CROW + ks * 32 + fcb);
                LDSM4(bfr[njp], rb);
            }
#pragma unroll
            for (int mi = 0; mi < 4; mi++)
#pragma unroll
                for (int njp = 0; njp < 2; njp++) {
                    mma1688_tf32(acc[mi][njp * 2],     a[mi], bfr[njp][0], bfr[njp][2]);
                    mma1688_tf32(acc[mi][njp * 2 + 1], a[mi], bfr[njp][1], bfr[njp][3]);
                }
        }
        CPA_WAIT0();
        __syncthreads();
    }

    const int g = lane >> 2, tc = lane & 3;
#pragma unroll
    for (int mi = 0; mi < 4; mi++) {
#pragma unroll
        for (int rr = 0; rr < 2; rr++) {
            const int oc = oc0 + wm * 64 + mi * 16 + g + rr * 8;
            const float bb = bias[oc];
            const size_t rbase = (((size_t)which * B_ + b) * C_ + oc) * L_ + l0;
#pragma unroll
            for (int nj = 0; nj < 4; nj++) {
                const int lc = wn * 32 + nj * 8 + tc * 2;
                float v0 = acc[mi][nj][rr * 2]     + bb;
                float v1 = acc[mi][nj][rr * 2 + 1] + bb;
                __nv_bfloat16 h0 = __float2bfloat16(v0);
                __nv_bfloat16 h1 = __float2bfloat16(v1);
                uint32_t ph = ((uint32_t)__bfloat16_as_ushort(h1) << 16) | __bfloat16_as_ushort(h0);
                uint32_t pl = packbf(v0 - __bfloat162float(h0), v1 - __bfloat162float(h1));
                *(uint32_t*)(g_oh + rbase + lc) = ph;
                *(uint32_t*)(g_ol + rbase + lc) = pl;
            }
        }
    }
}

// ---------------------------------------------------------------------------
// Tensor-core flash attention with double-buffered cp.async K/V stages.
// ---------------------------------------------------------------------------
#define QSTR    272
#define KSTR    144
#define A_QH    0
#define A_QL    (64 * QSTR)                  // 17408
#define A_KV0   (2 * 64 * QSTR)              // 34816 : per stage 4 arrays (KH,KL,VH,VL)
#define KVARR   (64 * KSTR)                  // 9216 per array
#define KVSTAGE (4 * KVARR)                  // 36864
#define SM_ATT  (A_KV0 + 2 * KVSTAGE)        // 108544

__global__ __launch_bounds__(256, 2) void attn_mma_kernel(float* __restrict__ out)
{
    extern __shared__ __align__(16) char sma[];
    const uint32_t sb = smem_u32(sma);
    const int tid = threadIdx.x, lane = tid & 31, w = tid >> 5;
    const int b = blockIdx.z, h = blockIdx.y, qt = blockIdx.x;
    const int q0 = qt * 128;
    const float scale = 0.04419417382415922f;   // 1/sqrt(512)

    const __nv_bfloat16* Qh = g_oh + (((size_t)0 * B_ + b) * C_ + h * DH_) * L_;
    const __nv_bfloat16* Ql = g_ol + (((size_t)0 * B_ + b) * C_ + h * DH_) * L_;
    const __nv_bfloat16* Kh = g_oh + (((size_t)1 * B_ + b) * C_ + h * DH_) * L_;
    const __nv_bfloat16* Kl = g_ol + (((size_t)1 * B_ + b) * C_ + h * DH_) * L_;
    const __nv_bfloat16* Vh = g_oh + (((size_t)2 * B_ + b) * C_ + h * DH_) * L_;
    const __nv_bfloat16* Vl = g_ol + (((size_t)2 * B_ + b) * C_ + h * DH_) * L_;

    // prefetch K/V tile 0 into stage 0 (async), overlap with Q loads
    auto load_kv = [&](int kt, int stg) {
        const int k0 = kt * 64;
        const uint32_t base = sb + A_KV0 + stg * KVSTAGE;
#pragma unroll
        for (int k = 0; k < 2; k++) {
            int e = tid + k * 256;
            int row = e >> 3, seg = e & 7;
            size_t so = (size_t)row * L_ + k0 + seg * 8;
            uint32_t d = base + row * KSTR + seg * 16;
            CPA16(d,              Kh + so);
            CPA16(d + KVARR,      Kl + so);
            CPA16(d + 2 * KVARR,  Vh + so);
            CPA16(d + 3 * KVARR,  Vl + so);
        }
        CPA_COMMIT();
    };

    load_kv(0, 0);

    // load Q tile [64 d][128 q] (sync; overlaps with in-flight cp.async)
#pragma unroll
    for (int e = tid; e < 1024; e += 256) {
        int row = e >> 4, seg = e & 15;
        size_t so = (size_t)row * L_ + q0 + seg * 8;
        *(uint4*)(sma + A_QH + row * QSTR + seg * 16) = *(const uint4*)(Qh + so);
        *(uint4*)(sma + A_QL + row * QSTR + seg * 16) = *(const uint4*)(Ql + so);
    }

    float mrow[2] = { -1e30f, -1e30f };
    float lrow[2] = { 0.f, 0.f };
    float oacc[8][4];
#pragma unroll
    for (int nj = 0; nj < 8; nj++)
#pragma unroll
        for (int r = 0; r < 4; r++) oacc[nj][r] = 0.f;

    const int t_dd  = (lane & 7) + ((lane >> 4) & 1) * 8;
    const int t_col = ((lane >> 3) & 1) * 8;

    CPA_WAIT0();
    __syncthreads();

    for (int kt = 0; kt < 16; kt++) {
        const int k0 = kt * 64;
        const uint32_t kvb = sb + A_KV0 + (kt & 1) * KVSTAGE;
        const bool domask = (kt == 15);

        // prefetch next tile into the other stage while computing this one
        if (kt < 15) load_kv(kt + 1, (kt + 1) & 1);

        // ---- S = Q K^T (3-pass split) ----
        float sf[8][4];
#pragma unroll
        for (int nj = 0; nj < 8; nj++)
#pragma unroll
            for (int r = 0; r < 4; r++) sf[nj][r] = 0.f;

#pragma unroll
        for (int dc = 0; dc < 4; dc++) {
            uint32_t ah[4], al[4];
            uint32_t aaddr = sb + A_QH + (uint32_t)((dc * 16 + t_dd) * QSTR + (w * 16 + t_col) * 2);
            LDSM4T(ah, aaddr);
            LDSM4T(al, aaddr + (A_QL - A_QH));
#pragma unroll
            for (int ks = 0; ks < 4; ks++) {
                uint32_t bh[4], bl[4];
                uint32_t baddr = kvb + (uint32_t)((dc * 16 + t_dd) * KSTR + (ks * 16 + t_col) * 2);
                LDSM4T(bh, baddr);
                LDSM4T(bl, baddr + KVARR);
#pragma unroll
                for (int od = 0; od < 2; od++) {
                    mma16816(sf[ks * 2 + od], ah, bh[od], bh[od + 2]);
                    mma16816(sf[ks * 2 + od], ah, bl[od], bl[od + 2]);
                    mma16816(sf[ks * 2 + od], al, bh[od], bh[od + 2]);
                }
            }
        }

        // scale (+ mask only on the final tile)
        if (domask) {
#pragma unroll
            for (int nj = 0; nj < 8; nj++)
#pragma unroll
                for (int r = 0; r < 4; r++) {
                    int col = k0 + nj * 8 + (lane & 3) * 2 + (r & 1);
                    sf[nj][r] = (col < LP_) ? sf[nj][r] * scale : -1e30f;
                }
        } else {
#pragma unroll
            for (int nj = 0; nj < 8; nj++)
#pragma unroll
                for (int r = 0; r < 4; r++) sf[nj][r] *= scale;
        }

        // online softmax
#pragma unroll
        for (int rr = 0; rr < 2; rr++) {
            float rm = -1e30f;
#pragma unroll
            for (int nj = 0; nj < 8; nj++)
                rm = fmaxf(rm, fmaxf(sf[nj][rr * 2], sf[nj][rr * 2 + 1]));
            rm = fmaxf(rm, __shfl_xor_sync(0xffffffffu, rm, 1));
            rm = fmaxf(rm, __shfl_xor_sync(0xffffffffu, rm, 2));
            const float mnew = fmaxf(mrow[rr], rm);
            const float corr = __expf(mrow[rr] - mnew);
            mrow[rr] = mnew;
            float ps = 0.f;
#pragma unroll
            for (int nj = 0; nj < 8; nj++) {
                float e0 = __expf(sf[nj][rr * 2] - mnew);
                float e1 = __expf(sf[nj][rr * 2 + 1] - mnew);
                sf[nj][rr * 2] = e0;
                sf[nj][rr * 2 + 1] = e1;
                ps += e0 + e1;
            }
            ps += __shfl_xor_sync(0xffffffffu, ps, 1);
            ps += __shfl_xor_sync(0xffffffffu, ps, 2);
            lrow[rr] = lrow[rr] * corr + ps;
#pragma unroll
            for (int nj = 0; nj < 8; nj++) {
                oacc[nj][rr * 2]     *= corr;
                oacc[nj][rr * 2 + 1] *= corr;
            }
        }

        // ---- O += P V^T (3-pass) ----
#pragma unroll
        for (int kc = 0; kc < 4; kc++) {
            uint32_t ap[4], alr[4];
            ap[0] = packbf(sf[2 * kc][0],     sf[2 * kc][1]);
            ap[1] = packbf(sf[2 * kc][2],     sf[2 * kc][3]);
            ap[2] = packbf(sf[2 * kc + 1][0], sf[2 * kc + 1][1]);
            ap[3] = packbf(sf[2 * kc + 1][2], sf[2 * kc + 1][3]);
#pragma unroll
            for (int i = 0; i < 4; i++) {
                float2 bk2 = __bfloat1622float2(*reinterpret_cast<__nv_bfloat162*>(&ap[i]));
                const int njs = 2 * kc + (i >> 1), rb2 = (i & 1) * 2;
                alr[i] = packbf(sf[njs][rb2] - bk2.x, sf[njs][rb2 + 1] - bk2.y);
            }
#pragma unroll
            for (int ds = 0; ds < 4; ds++) {
                uint32_t vh4[4], vl4[4];
                uint32_t vaddr = kvb + 2 * KVARR +
                    (uint32_t)((ds * 16 + (lane & 15)) * KSTR + kc * 32 + (lane >> 4) * 16);
                LDSM4(vh4, vaddr);
                LDSM4(vl4, vaddr + KVARR);
#pragma unroll
                for (int od = 0; od < 2; od++) {
                    mma16816(oacc[ds * 2 + od], ap,  vh4[od], vh4[od + 2]);
                    mma16816(oacc[ds * 2 + od], ap,  vl4[od], vl4[od + 2]);
                    mma16816(oacc[ds * 2 + od], alr, vh4[od], vh4[od + 2]);
                }
            }
        }

        CPA_WAIT0();
        __syncthreads();
    }

    // epilogue
    const int g = lane >> 2, tc = lane & 3;
#pragma unroll
    for (int rr = 0; rr < 2; rr++) {
        const int q = q0 + w * 16 + rr * 8 + g;
        if (q >= LP_) continue;
        const float inv = 1.f / lrow[rr];
#pragma unroll
        for (int nj = 0; nj < 8; nj++) {
            const int d = h * DH_ + nj * 8 + tc * 2;
            out[((size_t)b * C_ + d) * LP_ + q]     = oacc[nj][rr * 2] * inv;
            out[((size_t)b * C_ + d + 1) * LP_ + q] = oacc[nj][rr * 2 + 1] * inv;
        }
    }
}

// ---------------------------------------------------------------------------
extern "C" void kernel_launch(void* const* d_in, const int* in_sizes, int n_in,
                              void* d_out, int out_size)
{
    const float* x  = (const float*)d_in[0];
    const float* w0 = (const float*)d_in[1];
    const float* b0 = (const float*)d_in[2];
    const float* w1 = (const float*)d_in[3];
    const float* b1 = (const float*)d_in[4];
    const float* w2 = (const float*)d_in[5];
    const float* b2 = (const float*)d_in[6];
    float* out = (float*)d_out;

    wtrans_kernel<<<(3 * 3 * C_ * C_ + 255) / 256, 256>>>(w0, w1, w2);
    xtrans_kernel<<<dim3(L_ / 32, C_ / 32, B_), 256>>>(x);

    cudaFuncSetAttribute(conv_mma_kernel, cudaFuncAttributeMaxDynamicSharedMemorySize, SM_CONV);
    conv_mma_kernel<<<dim3(8, 12, 16), 256, SM_CONV>>>(b0, b1, b2);

    cudaFuncSetAttribute(attn_mma_kernel, cudaFuncAttributeMaxDynamicSharedMemorySize, SM_ATT);
    attn_mma_kernel<<<dim3(8, H_, B_), 256, SM_ATT>>>(out);
}